// round 14
// baseline (speedup 1.0000x reference)
#include <cuda_runtime.h>
#include <cuda_bf16.h>
#include <math.h>
#include <stdint.h>

#define TT    2048
#define NB    8
#define NC    128
#define NCOND 16
#define NL    10

#if defined(__CUDA_ARCH_FEAT_SM103_ALL) || defined(__CUDA_ARCH_FEAT_SM100_ALL) || defined(__CUDA_ARCH_FEAT_SM101_ALL)
#define HAS_TCGEN05 1
#else
#define HAS_TCGEN05 0
#endif

typedef unsigned long long u64;

// ---------------------------------------------------------------------------
// Device scratch
// ---------------------------------------------------------------------------
__device__ float g_h   [NB*TT*NC];
__device__ float g_skip[NB*TT*NC];
__device__ float g_out2[NB*TT*256];
__device__ float g_tcond[(size_t)NL*NB*TT*256];

__device__ __nv_bfloat16 g_hHi  [NB*TT*NC];
__device__ __nv_bfloat16 g_hLo  [NB*TT*NC];
__device__ __nv_bfloat16 g_WgHi [NL*3*256*128];
__device__ __nv_bfloat16 g_WgLo [NL*3*256*128];
__device__ __nv_bfloat16 g_WpHi [NL*256*128];
__device__ __nv_bfloat16 g_WpLo [NL*256*128];

__device__ __nv_bfloat16 g_skipHi[NB*TT*NC];
__device__ __nv_bfloat16 g_skipLo[NB*TT*NC];
__device__ __nv_bfloat16 g_W1tHi [3*2048*128];
__device__ __nv_bfloat16 g_W1tLo [3*2048*128];
__device__ __nv_bfloat16 g_W2tHi [3*256*2048];
__device__ __nv_bfloat16 g_W2tLo [3*256*2048];
__device__ __nv_bfloat16 g_out1Hi[(size_t)NB*TT*2048];
__device__ __nv_bfloat16 g_out1Lo[(size_t)NB*TT*2048];

// ---------------------------------------------------------------------------
// helpers
// ---------------------------------------------------------------------------
__device__ __forceinline__ uint32_t smem_to_u32(const void* p) {
    uint32_t a;
    asm("{ .reg .u64 t; cvta.to.shared.u64 t, %1; cvt.u32.u64 %0, t; }"
        : "=r"(a) : "l"(p));
    return a;
}
__device__ __forceinline__ float rcp_fast(float x) {
    float r; asm("rcp.approx.f32 %0, %1;" : "=f"(r) : "f"(x)); return r;
}
__device__ __forceinline__ float gate_act(float a, float x) {
    a = fminf(fmaxf(a, -15.f), 15.f);
    x = fminf(fmaxf(x, -15.f), 15.f);
    float E = __expf(2.f * a);
    float F = __expf(x);
    float r = rcp_fast((E + 1.f) * (F + 1.f));
    return (E - 1.f) * F * r;
}

#if HAS_TCGEN05
__device__ __forceinline__ uint32_t elect_one_pred() {
    uint32_t pred;
    asm volatile(
        "{\n\t.reg .pred p;\n\telect.sync _|p, 0xFFFFFFFF;\n\t"
        "selp.b32 %0, 1, 0, p;\n\t}" : "=r"(pred));
    return pred;
}

#define TCGEN05_ALLOC(smem_result_addr, nCols) \
    asm volatile("tcgen05.alloc.cta_group::1.sync.aligned.shared::cta.b32 [%0], %1;" \
        :: "r"((uint32_t)(smem_result_addr)), "r"((uint32_t)(nCols)) : "memory")
#define TCGEN05_DEALLOC(tmem_addr, nCols) \
    asm volatile("tcgen05.dealloc.cta_group::1.sync.aligned.b32 %0, %1;" \
        :: "r"(tmem_addr), "r"((uint32_t)(nCols)))
#define TCGEN05_RELINQUISH_ALLOC_PERMIT() \
    asm volatile("tcgen05.relinquish_alloc_permit.cta_group::1.sync.aligned;")
#define TCGEN05_COMMIT(mbar_smem_addr) \
    asm volatile("tcgen05.commit.cta_group::1.mbarrier::arrive::one.shared::cluster.b64 [%0];" \
        :: "r"((uint32_t)(mbar_smem_addr)) : "memory")
#define TCGEN05_FENCE_AFTER() \
    asm volatile("tcgen05.fence::after_thread_sync;" ::: "memory")
#define TCGEN05_WAIT_LD() \
    asm volatile("tcgen05.wait::ld.sync.aligned;" ::: "memory")
#define FENCE_PROXY_ASYNC_SHARED_CTA() \
    asm volatile("fence.proxy.async.shared::cta;" ::: "memory")
#define MBARRIER_INIT(mbar_smem_addr, count) \
    asm volatile("mbarrier.init.shared.b64 [%0], %1;" \
        :: "r"((uint32_t)(mbar_smem_addr)), "r"((uint32_t)(count)) : "memory")

#define MBARRIER_WAIT_PARITY(mbar_smem_addr, phase_parity) do { \
    uint32_t _mbar = (uint32_t)(mbar_smem_addr); \
    uint32_t _parity = (uint32_t)(phase_parity); \
    uint32_t _done; \
    asm volatile( \
        "{\n\t.reg .pred p;\n\t" \
        "mbarrier.try_wait.parity.acquire.cta.shared::cta.b64 p, [%1], %2;\n\t" \
        "selp.b32 %0, 1, 0, p;\n\t}" \
        : "=r"(_done) : "r"(_mbar), "r"(_parity) : "memory"); \
    if (!_done) { \
        asm volatile( \
            "{\n\t.reg .pred P1;\n\t" \
            "WAIT_LOOP_%=:\n\t" \
            "mbarrier.try_wait.parity.acquire.cta.shared::cta.b64 P1, [%0], %1, 0x989680;\n\t" \
            "@P1 bra.uni WAIT_DONE_%=;\n\t" \
            "bra.uni WAIT_LOOP_%=;\n\t" \
            "WAIT_DONE_%=:\n\t}" \
            :: "r"(_mbar), "r"(_parity) : "memory"); \
    } \
} while(0)

#define TCGEN05_LD_32X32B_X32(r, tmem_addr) \
    asm volatile( \
        "tcgen05.ld.sync.aligned.32x32b.x32.b32 " \
        "{%0, %1, %2, %3, %4, %5, %6, %7, " \
        " %8, %9, %10, %11, %12, %13, %14, %15, " \
        " %16, %17, %18, %19, %20, %21, %22, %23, " \
        " %24, %25, %26, %27, %28, %29, %30, %31}, [%32];" \
        : "=r"((r)[0]),  "=r"((r)[1]),  "=r"((r)[2]),  "=r"((r)[3]), \
          "=r"((r)[4]),  "=r"((r)[5]),  "=r"((r)[6]),  "=r"((r)[7]), \
          "=r"((r)[8]),  "=r"((r)[9]),  "=r"((r)[10]), "=r"((r)[11]), \
          "=r"((r)[12]), "=r"((r)[13]), "=r"((r)[14]), "=r"((r)[15]), \
          "=r"((r)[16]), "=r"((r)[17]), "=r"((r)[18]), "=r"((r)[19]), \
          "=r"((r)[20]), "=r"((r)[21]), "=r"((r)[22]), "=r"((r)[23]), \
          "=r"((r)[24]), "=r"((r)[25]), "=r"((r)[26]), "=r"((r)[27]), \
          "=r"((r)[28]), "=r"((r)[29]), "=r"((r)[30]), "=r"((r)[31]) \
        : "r"(tmem_addr))

static constexpr unsigned long long SMEM_DESC_BASE_SW128 =
    (2ull << 61) | (1ull << 46) | (64ull << 32) | (1ull << 16);
#define MAKE_SMEM_DESC(a) (SMEM_DESC_BASE_SW128 | ((unsigned long long)((a) >> 4) & 0x3FFF))

__device__ __forceinline__ void mma_bf16_ss(uint32_t d, u64 ad, u64 bd,
                                            uint32_t idesc, uint32_t en) {
    asm volatile(
        "{\n\t.reg .pred p;\n\t"
        "setp.ne.u32 p, %4, 0;\n\t"
        "tcgen05.mma.cta_group::1.kind::f16 [%0], %1, %2, %3, {%5, %5, %5, %5}, p;\n\t"
        "}"
        :: "r"(d), "l"(ad), "l"(bd), "r"(idesc), "r"(en), "r"(0u)
        : "memory");
}

static constexpr uint32_t GEMM_IDESC =
    (1u << 4) | (1u << 7) | (1u << 10) | ((128u / 8) << 17) | ((128u / 16) << 24);
static constexpr uint32_t IDESC_N256 =
    (1u << 4) | (1u << 7) | (1u << 10) | ((256u / 8) << 17) | ((128u / 16) << 24);
#endif // HAS_TCGEN05

// ---------------------------------------------------------------------------
__global__ __launch_bounds__(256) void k_init(const float* __restrict__ x,
                                              const float* __restrict__ Wc,
                                              const float* __restrict__ bc) {
    int idx = blockIdx.x * 256 + threadIdx.x;
    int c  = idx & (NC - 1);
    int bt = idx >> 7;
    float v = x[bt] * Wc[c] + bc[c];
    g_h[idx]    = v;
    g_skip[idx] = 0.f;
    __nv_bfloat16 h = __float2bfloat16(v);
    g_hHi[idx] = h;
    g_hLo[idx] = __float2bfloat16(v - __bfloat162float(h));
}

// ---------------------------------------------------------------------------
// merged stack weight conversion: blocks [0,960) = gates (Wt/Ws),
// blocks [960,1280) = post (Wskip/Wres). 256 threads (tx=tid&31, ty=tid>>5).
// ---------------------------------------------------------------------------
__global__ __launch_bounds__(256) void k_cvtStack(
    const float* __restrict__ Wt, const float* __restrict__ Ws,
    const float* __restrict__ Wskip, const float* __restrict__ Wres)
{
    __shared__ float t[32][33];
    int id = blockIdx.x;
    int tid = threadIdx.x;
    int tx = tid & 31, ty = tid >> 5;

    const float* src;
    __nv_bfloat16 *dhi, *dlo;
    int co0, ci0, gate;
    size_t obase;
    if (id < 960) {
        int z = id / 16, rem = id % 16;
        co0 = (rem & 3) * 32; ci0 = (rem >> 2) * 32;
        int lt = z >> 1; gate = z & 1;
        src = (gate ? Ws : Wt) + (size_t)lt * 128 * 128;
        dhi = g_WgHi; dlo = g_WgLo;
        obase = (size_t)lt * 256 * 128;
    } else {
        int id2 = id - 960;
        int z = id2 / 16, rem = id2 % 16;
        co0 = (rem & 3) * 32; ci0 = (rem >> 2) * 32;
        int l = z >> 1; gate = z & 1;
        src = (gate ? Wres : Wskip) + (size_t)l * 128 * 128;
        dhi = g_WpHi; dlo = g_WpLo;
        obase = (size_t)l * 256 * 128;
    }
    #pragma unroll
    for (int r = 0; r < 4; r++)
        t[ty + r*8][tx] = src[(ci0 + ty + r*8) * 128 + co0 + tx];
    __syncthreads();
    #pragma unroll
    for (int r = 0; r < 4; r++) {
        float v = t[tx][ty + r*8];
        int n = gate * 128 + co0 + ty + r*8;
        size_t o = obase + (size_t)n * 128 + ci0 + tx;
        __nv_bfloat16 h = __float2bfloat16(v);
        dhi[o] = h;
        dlo[o] = __float2bfloat16(v - __bfloat162float(h));
    }
}

__global__ void k_cvtWhead(const float* __restrict__ W1, const float* __restrict__ W2,
                           __nv_bfloat16* __restrict__ w1h, __nv_bfloat16* __restrict__ w1l,
                           __nv_bfloat16* __restrict__ w2h, __nv_bfloat16* __restrict__ w2l) {
    __shared__ float t[32][33];
    int id = blockIdx.x;
    const float* src; __nv_bfloat16 *dhi, *dlo;
    int K, N, n0, k0, tap;
    if (id < 768) {
        tap = id / 256; int rem = id % 256;
        n0 = (rem & 63) * 32; k0 = (rem >> 6) * 32;
        src = W1; dhi = w1h; dlo = w1l; K = 128; N = 2048;
    } else {
        id -= 768;
        tap = id / 512; int rem = id % 512;
        n0 = (rem & 7) * 32; k0 = (rem >> 3) * 32;
        src = W2; dhi = w2h; dlo = w2l; K = 2048; N = 256;
    }
    int tx = threadIdx.x, ty = threadIdx.y;
    #pragma unroll
    for (int r = 0; r < 4; r++)
        t[ty + r*8][tx] = src[((size_t)tap*K + k0 + ty + r*8) * N + n0 + tx];
    __syncthreads();
    #pragma unroll
    for (int r = 0; r < 4; r++) {
        float v = t[tx][ty + r*8];
        __nv_bfloat16 h = __float2bfloat16(v);
        __nv_bfloat16 l = __float2bfloat16(v - __bfloat162float(h));
        size_t o = ((size_t)tap*N + n0 + ty + r*8) * K + k0 + tx;
        dhi[o] = h; dlo[o] = l;
    }
}

// ---------------------------------------------------------------------------
__global__ __launch_bounds__(256) void k_condpre(
    const float* __restrict__ cond,
    const float* __restrict__ Dt, const float* __restrict__ Ds,
    const float* __restrict__ Bt, const float* __restrict__ Bs,
    const float* __restrict__ bt, const float* __restrict__ bs, int l)
{
    const int tid = threadIdx.x;
    const int co = (tid & 31) << 2;
    const int gate = (tid >> 5) & 1;
    const int tq = tid >> 6;
    const int t0 = blockIdx.x * 8 + tq;

    __shared__ float sc[NB][NCOND];
    if (tid < NB * NCOND) sc[tid >> 4][tid & 15] = cond[tid];
    __syncthreads();

    const float* D  = gate ? Ds : Dt;
    const float* Bm = gate ? Bs : Bt;
    float4 bias = *(const float4*)((gate ? bs : bt) + l * 128 + co);

    float4 acc[2][NB];
    #pragma unroll
    for (int tt = 0; tt < 2; tt++)
        #pragma unroll
        for (int b = 0; b < NB; b++) acc[tt][b] = make_float4(0.f, 0.f, 0.f, 0.f);

    #pragma unroll 4
    for (int c = 0; c < NCOND; c++) {
        size_t base = (((size_t)l * NCOND + c) * TT + t0) * 128 + co;
        float4 d0 = *(const float4*)(D + base);
        float4 d1 = *(const float4*)(D + base + 4 * 128);
        #pragma unroll
        for (int b = 0; b < NB; b++) {
            float s = sc[b][c];
            acc[0][b].x = fmaf(s, d0.x, acc[0][b].x);
            acc[0][b].y = fmaf(s, d0.y, acc[0][b].y);
            acc[0][b].z = fmaf(s, d0.z, acc[0][b].z);
            acc[0][b].w = fmaf(s, d0.w, acc[0][b].w);
            acc[1][b].x = fmaf(s, d1.x, acc[1][b].x);
            acc[1][b].y = fmaf(s, d1.y, acc[1][b].y);
            acc[1][b].z = fmaf(s, d1.z, acc[1][b].z);
            acc[1][b].w = fmaf(s, d1.w, acc[1][b].w);
        }
    }
    #pragma unroll
    for (int tt = 0; tt < 2; tt++) {
        int t = t0 + tt * 4;
        float4 bm = *(const float4*)(Bm + ((size_t)l * TT + t) * 128 + co);
        bm.x += bias.x; bm.y += bias.y; bm.z += bias.z; bm.w += bias.w;
        #pragma unroll
        for (int b = 0; b < NB; b++) {
            float4 v = acc[tt][b];
            v.x += bm.x; v.y += bm.y; v.z += bm.z; v.w += bm.w;
            *(float4*)(g_tcond + (((size_t)l * NB + b) * TT + t) * 256
                       + gate * 128 + co) = v;
        }
    }
}

// ---------------------------------------------------------------------------
// Fused residual layer (unchanged)
// ---------------------------------------------------------------------------
#define LAYER_SMEM 200704

__global__ __launch_bounds__(256, 1) void k_layer(
    int l, int d, const float* __restrict__ bskip, const float* __restrict__ bres)
{
#if HAS_TCGEN05
    extern __shared__ char dsm[];
    const int tid = threadIdx.x;
    const int wid = tid >> 5;
    const int lane = tid & 31;

    uint32_t raw = smem_to_u32(dsm);
    uint32_t abase = (raw + 1023) & ~1023u;
    char* hdr = dsm + (abase - raw);
    char* G   = hdr + 2048;
    const uint32_t hdr_a = abase;
    const uint32_t G_a   = abase + 2048;

    const int b  = blockIdx.x >> 4;
    const int t0 = (blockIdx.x & 15) << 7;

    if (tid == 0) {
        MBARRIER_INIT(hdr_a + 8, 1);
        MBARRIER_INIT(hdr_a + 16, 1);
    }
    if (wid == 0) TCGEN05_ALLOC(hdr_a, 512);
    __syncthreads();

    uint32_t tmem;
    asm volatile("ld.shared.b32 %0, [%1];" : "=r"(tmem) : "r"(hdr_a));

    int phase[2] = {0, 0};

    for (int ch = 0; ch < 6; ch++) {
        const int buf = ch & 1;
        char* Gb = G + buf * 98304;
        const uint32_t Gb_a = G_a + buf * 98304;
        const int tap = ch >> 1;
        const int ci0 = (ch & 1) << 6;

        uint4 va[8];
        const int r2 = tid >> 1, half = tid & 1;
        {
            int trow = t0 + r2 + (tap - 1) * d;
            bool ok = (unsigned)trow < (unsigned)TT;
            size_t goff = ((size_t)(b * TT + (ok ? trow : 0))) * NC + ci0 + half * 32;
            #pragma unroll
            for (int q = 0; q < 4; q++) {
                if (ok) {
                    va[q]     = *(const uint4*)(g_hHi + goff + q * 8);
                    va[4 + q] = *(const uint4*)(g_hLo + goff + q * 8);
                } else {
                    va[q] = make_uint4(0,0,0,0);
                    va[4 + q] = make_uint4(0,0,0,0);
                }
            }
        }
        uint4 wb[16];
        {
            size_t woff = (((size_t)(l * 3 + tap)) * 256 + tid) * 128 + ci0;
            #pragma unroll
            for (int q = 0; q < 8; q++) {
                wb[q]     = *(const uint4*)(g_WgHi + woff + q * 8);
                wb[8 + q] = *(const uint4*)(g_WgLo + woff + q * 8);
            }
        }

        if (ch >= 2) {
            MBARRIER_WAIT_PARITY(hdr_a + 8 + 8 * buf, phase[buf]);
            phase[buf] ^= 1;
        }

        #pragma unroll
        for (int q = 0; q < 4; q++) {
            int c = half * 4 + q;
            uint32_t so = r2 * 128 + (((uint32_t)(c ^ (r2 & 7))) << 4);
            *(uint4*)(Gb + so)         = va[q];
            *(uint4*)(Gb + 16384 + so) = va[4 + q];
        }
        #pragma unroll
        for (int q = 0; q < 8; q++) {
            uint32_t so = tid * 128 + (((uint32_t)(q ^ (tid & 7))) << 4);
            *(uint4*)(Gb + 32768 + so) = wb[q];
            *(uint4*)(Gb + 65536 + so) = wb[8 + q];
        }
        FENCE_PROXY_ASYNC_SHARED_CTA();
        __syncthreads();

        if (wid == 0 && elect_one_pred()) {
            u64 dAh = MAKE_SMEM_DESC(Gb_a);
            u64 dAl = MAKE_SMEM_DESC(Gb_a + 16384);
            u64 dBh = MAKE_SMEM_DESC(Gb_a + 32768);
            u64 dBl = MAKE_SMEM_DESC(Gb_a + 65536);
            uint32_t en = (ch != 0);
            #pragma unroll
            for (int ks = 0; ks < 4; ks++) {
                mma_bf16_ss(tmem, dAh + 2*ks, dBh + 2*ks, IDESC_N256, en); en = 1;
                mma_bf16_ss(tmem, dAh + 2*ks, dBl + 2*ks, IDESC_N256, 1);
                mma_bf16_ss(tmem, dAl + 2*ks, dBh + 2*ks, IDESC_N256, 1);
            }
            TCGEN05_COMMIT(hdr_a + 8 + 8 * buf);
        }
    }

    MBARRIER_WAIT_PARITY(hdr_a + 8,  phase[0]);
    MBARRIER_WAIT_PARITY(hdr_a + 16, phase[1]);
    const int postPh = phase[0] ^ 1;
    TCGEN05_FENCE_AFTER();
    __syncthreads();

    float* tcS = (float*)(G + 65536);
    {
        const float* tcg = g_tcond + (((size_t)l * NB + b) * TT + t0) * 256;
        #pragma unroll
        for (int k = 0; k < 32; k++) {
            int i4 = tid + k * 256;
            int row = i4 >> 6, c4 = (i4 & 63) << 2;
            float4 v = *(const float4*)(tcg + (size_t)row * 256 + c4);
            *(float4*)(tcS + row * 260 + c4) = v;
        }
    }
    __syncthreads();

    {
        const int row = (wid & 3) * 32 + lane;
        const int cho = (wid >> 2) * 64;
        const float* trow_ = tcS + row * 260;
        #pragma unroll 1
        for (int half2 = 0; half2 < 2; half2++) {
            int c0 = cho + half2 * 32;
            uint32_t rt[32], rs[32];
            TCGEN05_LD_32X32B_X32(rt, tmem + c0);
            TCGEN05_LD_32X32B_X32(rs, tmem + 128 + c0);
            TCGEN05_WAIT_LD();
            #pragma unroll
            for (int j = 0; j < 32; j += 4) {
                int c = c0 + j;
                float4 ta = *(const float4*)(trow_ + c);
                float4 tx = *(const float4*)(trow_ + 128 + c);
                float av[4] = {__uint_as_float(rt[j])   + ta.x,
                               __uint_as_float(rt[j+1]) + ta.y,
                               __uint_as_float(rt[j+2]) + ta.z,
                               __uint_as_float(rt[j+3]) + ta.w};
                float xv[4] = {__uint_as_float(rs[j])   + tx.x,
                               __uint_as_float(rs[j+1]) + tx.y,
                               __uint_as_float(rs[j+2]) + tx.z,
                               __uint_as_float(rs[j+3]) + tx.w};
                __nv_bfloat16 hv[4], lv[4];
                #pragma unroll
                for (int q = 0; q < 4; q++) {
                    float gv = gate_act(av[q], xv[q]);
                    hv[q] = __float2bfloat16(gv);
                    lv[q] = __float2bfloat16(gv - __bfloat162float(hv[q]));
                }
                uint32_t off = row * 128 + (c & 63) * 2;
                off ^= (off >> 3) & 0x70;
                char* atp = G + ((c >> 6) * 32768);
                *(uint2*)(atp + off)         = *(const uint2*)hv;
                *(uint2*)(atp + 16384 + off) = *(const uint2*)lv;
            }
        }
    }
    __syncthreads();

    {
        size_t woff = ((size_t)l * 256 + tid) * 128;
        #pragma unroll
        for (int cc = 0; cc < 2; cc++) {
            char* dst = G + 65536 + cc * 65536;
            #pragma unroll
            for (int q = 0; q < 8; q++) {
                uint32_t so = tid * 128 + (((uint32_t)(q ^ (tid & 7))) << 4);
                *(uint4*)(dst + so)         = *(const uint4*)(g_WpHi + woff + cc*64 + q*8);
                *(uint4*)(dst + 32768 + so) = *(const uint4*)(g_WpLo + woff + cc*64 + q*8);
            }
        }
    }
    FENCE_PROXY_ASYNC_SHARED_CTA();
    __syncthreads();

    if (wid == 0 && elect_one_pred()) {
        uint32_t en = 0;
        #pragma unroll
        for (int cc = 0; cc < 2; cc++) {
            u64 dAh = MAKE_SMEM_DESC(G_a + cc * 32768);
            u64 dAl = MAKE_SMEM_DESC(G_a + cc * 32768 + 16384);
            u64 dBh = MAKE_SMEM_DESC(G_a + 65536 + cc * 65536);
            u64 dBl = MAKE_SMEM_DESC(G_a + 65536 + cc * 65536 + 32768);
            #pragma unroll
            for (int ks = 0; ks < 4; ks++) {
                mma_bf16_ss(tmem + 256, dAh + 2*ks, dBh + 2*ks, IDESC_N256, en); en = 1;
                mma_bf16_ss(tmem + 256, dAh + 2*ks, dBl + 2*ks, IDESC_N256, 1);
                mma_bf16_ss(tmem + 256, dAl + 2*ks, dBh + 2*ks, IDESC_N256, 1);
            }
        }
        TCGEN05_COMMIT(hdr_a + 8);
    }
    MBARRIER_WAIT_PARITY(hdr_a + 8, postPh);
    TCGEN05_FENCE_AFTER();
    __syncthreads();

    float* st = (float*)G;
    {
        const int row = (wid & 3) * 32 + lane;
        const int g2 = wid >> 2;
        #pragma unroll 1
        for (int bt2 = 0; bt2 < 2; bt2++) {
            int c0 = g2 * 128 + bt2 * 64;
            uint32_t ra[32], rb[32];
            TCGEN05_LD_32X32B_X32(ra, tmem + 256 + c0);
            TCGEN05_LD_32X32B_X32(rb, tmem + 256 + c0 + 32);
            TCGEN05_WAIT_LD();
            #pragma unroll
            for (int j = 0; j < 32; j += 4) {
                float4 v1 = make_float4(__uint_as_float(ra[j]),   __uint_as_float(ra[j+1]),
                                        __uint_as_float(ra[j+2]), __uint_as_float(ra[j+3]));
                float4 v2 = make_float4(__uint_as_float(rb[j]),   __uint_as_float(rb[j+1]),
                                        __uint_as_float(rb[j+2]), __uint_as_float(rb[j+3]));
                *(float4*)(st + row * 260 + c0 + j)      = v1;
                *(float4*)(st + row * 260 + c0 + 32 + j) = v2;
            }
        }
    }
    __syncthreads();

    {
        const size_t gbase = ((size_t)(b * TT + t0)) * NC;
        const bool lastL = (l == NL - 1);
        #pragma unroll
        for (int k = 0; k < 16; k++) {
            int e = tid + k * 256;
            int row = e >> 5, c4 = (e & 31) << 2;
            float4 dsk = *(const float4*)(st + row * 260 + c4);
            float4 bk4 = *(const float4*)(bskip + l * 128 + c4);
            size_t go = gbase + (size_t)row * NC + c4;
            float4 sk = *(const float4*)(g_skip + go);
            sk.x += dsk.x + bk4.x; sk.y += dsk.y + bk4.y;
            sk.z += dsk.z + bk4.z; sk.w += dsk.w + bk4.w;
            if (!lastL) {
                float4 dre = *(const float4*)(st + row * 260 + 128 + c4);
                float4 br4 = *(const float4*)(bres  + l * 128 + c4);
                float4 hh = *(const float4*)(g_h + go);
                hh.x += dre.x + br4.x; hh.y += dre.y + br4.y;
                hh.z += dre.z + br4.z; hh.w += dre.w + br4.w;
                *(float4*)(g_skip + go) = sk;
                *(float4*)(g_h + go) = hh;
                float hq[4] = {hh.x, hh.y, hh.z, hh.w};
                __nv_bfloat16 hv[4], lv[4];
                #pragma unroll
                for (int q = 0; q < 4; q++) {
                    hv[q] = __float2bfloat16(hq[q]);
                    lv[q] = __float2bfloat16(hq[q] - __bfloat162float(hv[q]));
                }
                *(uint2*)(g_hHi + go) = *(const uint2*)hv;
                *(uint2*)(g_hLo + go) = *(const uint2*)lv;
            } else {
                float sq[4] = {sk.x, sk.y, sk.z, sk.w};
                __nv_bfloat16 hv[4], lv[4];
                #pragma unroll
                for (int q = 0; q < 4; q++) {
                    hv[q] = __float2bfloat16(sq[q]);
                    lv[q] = __float2bfloat16(sq[q] - __bfloat162float(hv[q]));
                }
                *(uint2*)(g_skipHi + go) = *(const uint2*)hv;
                *(uint2*)(g_skipLo + go) = *(const uint2*)lv;
            }
        }
    }
    __syncthreads();
    if (wid == 0) {
        TCGEN05_RELINQUISH_ALLOC_PERMIT();
        TCGEN05_DEALLOC(tmem, 512);
    }
#endif // HAS_TCGEN05
}

// ---------------------------------------------------------------------------
// Head GEMM-conv3, TWO N-tiles per CTA (round-13 validated).
// ---------------------------------------------------------------------------
#define GEMM_SMEM 200704

template<bool WB16>
__global__ __launch_bounds__(256, 1) void k_gemm(
    const __nv_bfloat16* __restrict__ aHi, const __nv_bfloat16* __restrict__ aLo,
    const __nv_bfloat16* __restrict__ wHi, const __nv_bfloat16* __restrict__ wLo,
    const float* __restrict__ bias,
    __nv_bfloat16* __restrict__ oHi, __nv_bfloat16* __restrict__ oLo,
    float* __restrict__ oF, int Cin, int CO)
{
#if HAS_TCGEN05
    extern __shared__ char dsm[];
    const int tid = threadIdx.x;
    const int wid = tid >> 5;
    const int lane = tid & 31;

    uint32_t raw = smem_to_u32(dsm);
    uint32_t abase = (raw + 1023) & ~1023u;
    char* hdr   = dsm + (abase - raw);
    char* G     = hdr + 2048;
    const uint32_t hdr_a = abase;
    const uint32_t G_a   = abase + 2048;
    float* sbias = (float*)(hdr + 1024);

    const int b  = blockIdx.x >> 4;
    const int t0 = (blockIdx.x & 15) * 128;
    const int n0 = blockIdx.y * 256;

    if (tid == 0) {
        MBARRIER_INIT(hdr_a + 8, 1);
        MBARRIER_INIT(hdr_a + 16, 1);
    }
    if (wid == 0) TCGEN05_ALLOC(hdr_a, 256);
    sbias[tid] = bias[n0 + tid];
    __syncthreads();

    uint32_t tmem;
    asm volatile("ld.shared.b32 %0, [%1];" : "=r"(tmem) : "r"(hdr_a));

    const int nci = Cin >> 6;
    const int nchunks = 3 * nci;
    const size_t aBatch = (size_t)b * TT * Cin;

    int phase[2] = {0, 0};

    for (int ch = 0; ch < nchunks; ch++) {
        const int buf = ch & 1;
        char* tb = G + buf * 98304;
        const uint32_t tb_a = G_a + buf * 98304;

        const int tap = ch / nci;
        const int ci0 = (ch - tap * nci) << 6;
        const size_t bBase0 = ((size_t)tap * CO + n0) * Cin + ci0;
        const int c = tid & 7;

        uint4 va[8], vb0[8];
        #pragma unroll
        for (int p = 0; p < 4; p++) {
            int r = p * 32 + (tid >> 3);
            int trow = t0 + r + tap - 1;
            if ((unsigned)trow < (unsigned)TT) {
                size_t off = aBatch + (size_t)trow * Cin + ci0 + c * 8;
                va[p]     = *(const uint4*)(aHi + off);
                va[4 + p] = *(const uint4*)(aLo + off);
            } else {
                va[p] = make_uint4(0,0,0,0);
                va[4 + p] = make_uint4(0,0,0,0);
            }
            size_t bo = bBase0 + (size_t)r * Cin + c * 8;
            vb0[p]     = *(const uint4*)(wHi + bo);
            vb0[4 + p] = *(const uint4*)(wLo + bo);
        }

        if (ch >= 2) {
            MBARRIER_WAIT_PARITY(hdr_a + 8 + 8 * buf, phase[buf]);
            phase[buf] ^= 1;
        }

        #pragma unroll
        for (int p = 0; p < 4; p++) {
            int r = p * 32 + (tid >> 3);
            uint32_t so = r * 128 + (((uint32_t)(c ^ (r & 7))) << 4);
            *(uint4*)(tb + so)         = va[p];
            *(uint4*)(tb + 16384 + so) = va[4 + p];
            *(uint4*)(tb + 32768 + so) = vb0[p];
            *(uint4*)(tb + 49152 + so) = vb0[4 + p];
        }
        {
            const size_t bBase1 = bBase0 + (size_t)128 * Cin;
            #pragma unroll
            for (int p = 0; p < 4; p++) {
                int r = p * 32 + (tid >> 3);
                size_t bo = bBase1 + (size_t)r * Cin + c * 8;
                uint4 h4 = *(const uint4*)(wHi + bo);
                uint4 l4 = *(const uint4*)(wLo + bo);
                uint32_t so = r * 128 + (((uint32_t)(c ^ (r & 7))) << 4);
                *(uint4*)(tb + 65536 + so) = h4;
                *(uint4*)(tb + 81920 + so) = l4;
            }
        }
        FENCE_PROXY_ASYNC_SHARED_CTA();
        __syncthreads();

        if (wid == 0 && elect_one_pred()) {
            u64 dAh  = MAKE_SMEM_DESC(tb_a);
            u64 dAl  = MAKE_SMEM_DESC(tb_a + 16384);
            u64 dB0h = MAKE_SMEM_DESC(tb_a + 32768);
            u64 dB0l = MAKE_SMEM_DESC(tb_a + 49152);
            u64 dB1h = MAKE_SMEM_DESC(tb_a + 65536);
            u64 dB1l = MAKE_SMEM_DESC(tb_a + 81920);
            uint32_t en = (ch != 0);
            #pragma unroll
            for (int ks = 0; ks < 4; ks++) {
                mma_bf16_ss(tmem,       dAh + 2*ks, dB0h + 2*ks, GEMM_IDESC, en);
                mma_bf16_ss(tmem + 128, dAh + 2*ks, dB1h + 2*ks, GEMM_IDESC, en);
                en = 1;
                mma_bf16_ss(tmem,       dAh + 2*ks, dB0l + 2*ks, GEMM_IDESC, 1);
                mma_bf16_ss(tmem,       dAl + 2*ks, dB0h + 2*ks, GEMM_IDESC, 1);
                mma_bf16_ss(tmem + 128, dAh + 2*ks, dB1l + 2*ks, GEMM_IDESC, 1);
                mma_bf16_ss(tmem + 128, dAl + 2*ks, dB1h + 2*ks, GEMM_IDESC, 1);
            }
            TCGEN05_COMMIT(hdr_a + 8 + 8 * buf);
        }
    }

    MBARRIER_WAIT_PARITY(hdr_a + 8,  phase[0]);
    MBARRIER_WAIT_PARITY(hdr_a + 16, phase[1]);
    TCGEN05_FENCE_AFTER();
    __syncthreads();

    #pragma unroll 1
    for (int nt = 0; nt < 2; nt++) {
        const uint32_t dbase = tmem + nt * 128;
        const int nb = n0 + nt * 128;
        if (WB16) {
            char* hiS = G;
            char* loS = G + 34816;
            {
                const int m = (wid & 3) * 32 + lane;
                const int cg = (wid >> 2) * 64;
                #pragma unroll 1
                for (int half2 = 0; half2 < 2; half2++) {
                    int c0 = cg + half2 * 32;
                    uint32_t r32[32];
                    TCGEN05_LD_32X32B_X32(r32, dbase + c0);
                    TCGEN05_WAIT_LD();
                    #pragma unroll
                    for (int j = 0; j < 32; j += 2) {
                        __nv_bfloat16 hv[2], lv[2];
                        #pragma unroll
                        for (int q = 0; q < 2; q++) {
                            float v = __uint_as_float(r32[j+q]) + sbias[nt*128 + c0 + j + q];
                            v = fmaxf(v, 0.f);
                            hv[q] = __float2bfloat16(v);
                            lv[q] = __float2bfloat16(v - __bfloat162float(hv[q]));
                        }
                        uint32_t so = m * 272 + (c0 + j) * 2;
                        *(uint32_t*)(hiS + so) = *(const uint32_t*)hv;
                        *(uint32_t*)(loS + so) = *(const uint32_t*)lv;
                    }
                }
            }
            __syncthreads();
            #pragma unroll
            for (int k = 0; k < 8; k++) {
                int e = tid + k * 256;
                int row = e >> 4, cu = e & 15;
                uint4 h4 = *(const uint4*)(hiS + row * 272 + cu * 16);
                uint4 l4 = *(const uint4*)(loS + row * 272 + cu * 16);
                size_t o = (size_t)(b * TT + t0 + row) * CO + nb + cu * 8;
                *(uint4*)(oHi + o) = h4;
                *(uint4*)(oLo + o) = l4;
            }
            __syncthreads();
        } else {
            float* fS = (float*)G;
            {
                const int m = (wid & 3) * 32 + lane;
                const int cg = (wid >> 2) * 64;
                #pragma unroll 1
                for (int half2 = 0; half2 < 2; half2++) {
                    int c0 = cg + half2 * 32;
                    uint32_t r32[32];
                    TCGEN05_LD_32X32B_X32(r32, dbase + c0);
                    TCGEN05_WAIT_LD();
                    #pragma unroll
                    for (int j = 0; j < 32; j += 4) {
                        float4 v;
                        v.x = fmaxf(__uint_as_float(r32[j])   + sbias[nt*128 + c0+j],   0.f);
                        v.y = fmaxf(__uint_as_float(r32[j+1]) + sbias[nt*128 + c0+j+1], 0.f);
                        v.z = fmaxf(__uint_as_float(r32[j+2]) + sbias[nt*128 + c0+j+2], 0.f);
                        v.w = fmaxf(__uint_as_float(r32[j+3]) + sbias[nt*128 + c0+j+3], 0.f);
                        *(float4*)(fS + m * 132 + c0 + j) = v;
                    }
                }
            }
            __syncthreads();
            #pragma unroll
            for (int k = 0; k < 16; k++) {
                int e = tid + k * 256;
                int row = e >> 5, c4 = (e & 31) << 2;
                float4 v = *(const float4*)(fS + row * 132 + c4);
                *(float4*)(oF + (size_t)(b * TT + t0 + row) * CO + nb + c4) = v;
            }
            __syncthreads();
        }
    }

    if (wid == 0) {
        TCGEN05_RELINQUISH_ALLOC_PERMIT();
        TCGEN05_DEALLOC(tmem, 256);
    }
#endif // HAS_TCGEN05
}

// ---------------------------------------------------------------------------
__global__ __launch_bounds__(128) void k_head3(const float* __restrict__ W3,
                                               const float* __restrict__ b3,
                                               float* __restrict__ out)
{
    int row  = blockIdx.x * 4 + (threadIdx.x >> 5);
    int lane = threadIdx.x & 31;
    const float* p = g_out2 + (size_t)row * 256;
    float s = 0.f;
    #pragma unroll
    for (int i = 0; i < 8; i++) s = fmaf(p[lane + 32 * i], W3[lane + 32 * i], s);
    #pragma unroll
    for (int o = 16; o; o >>= 1) s += __shfl_xor_sync(0xffffffffu, s, o);
    if (lane == 0) out[row] = tanhf(s + b3[0]);
}

// ---------------------------------------------------------------------------
static cudaStream_t s_side = nullptr;
static cudaEvent_t  s_evFork = nullptr;
static cudaEvent_t  s_evW = nullptr;
static cudaEvent_t  s_evL[NL];

extern "C" void kernel_launch(void* const* d_in, const int* in_sizes, int n_in,
                              void* d_out, int out_size) {
    const float* x     = (const float*)d_in[0];
    const float* cond  = (const float*)d_in[1];
    const float* Wc    = (const float*)d_in[2];
    const float* bc    = (const float*)d_in[3];
    const float* Wt    = (const float*)d_in[4];
    const float* bt    = (const float*)d_in[5];
    const float* Ws    = (const float*)d_in[6];
    const float* bs    = (const float*)d_in[7];
    const float* Dt    = (const float*)d_in[8];
    const float* Bt    = (const float*)d_in[9];
    const float* Ds    = (const float*)d_in[10];
    const float* Bs    = (const float*)d_in[11];
    const float* Wskip = (const float*)d_in[12];
    const float* bskip = (const float*)d_in[13];
    const float* Wres  = (const float*)d_in[14];
    const float* bres  = (const float*)d_in[15];
    const float* W1    = (const float*)d_in[16];
    const float* b1    = (const float*)d_in[17];
    const float* W2    = (const float*)d_in[18];
    const float* b2    = (const float*)d_in[19];
    const float* W3    = (const float*)d_in[20];
    const float* b3    = (const float*)d_in[21];
    float* out = (float*)d_out;

    if (!s_side) {
        cudaStreamCreateWithFlags(&s_side, cudaStreamNonBlocking);
        cudaEventCreateWithFlags(&s_evFork, cudaEventDisableTiming);
        cudaEventCreateWithFlags(&s_evW, cudaEventDisableTiming);
        for (int l = 0; l < NL; l++)
            cudaEventCreateWithFlags(&s_evL[l], cudaEventDisableTiming);
    }

    cudaFuncSetAttribute(k_layer, cudaFuncAttributeMaxDynamicSharedMemorySize, LAYER_SMEM);
    cudaFuncSetAttribute(k_gemm<true>,  cudaFuncAttributeMaxDynamicSharedMemorySize, GEMM_SMEM);
    cudaFuncSetAttribute(k_gemm<false>, cudaFuncAttributeMaxDynamicSharedMemorySize, GEMM_SMEM);

    __nv_bfloat16 *skipHi, *skipLo, *w1h, *w1l, *w2h, *w2l, *o1h, *o1l;
    float* out2p;
    cudaGetSymbolAddress((void**)&skipHi, g_skipHi);
    cudaGetSymbolAddress((void**)&skipLo, g_skipLo);
    cudaGetSymbolAddress((void**)&w1h, g_W1tHi);
    cudaGetSymbolAddress((void**)&w1l, g_W1tLo);
    cudaGetSymbolAddress((void**)&w2h, g_W2tHi);
    cudaGetSymbolAddress((void**)&w2l, g_W2tLo);
    cudaGetSymbolAddress((void**)&o1h, g_out1Hi);
    cudaGetSymbolAddress((void**)&o1l, g_out1Lo);
    cudaGetSymbolAddress((void**)&out2p, g_out2);

    const int dil[NL] = {1, 2, 4, 8, 16, 32, 64, 128, 256, 512};

    // main stream; k_layer(0) is the 4th launch (ncu profiles the 4th)
    k_condpre<<<TT/8, 256>>>(cond, Dt, Ds, Bt, Bs, bt, bs, 0);     // 1
    k_cvtStack<<<1280, 256>>>(Wt, Ws, Wskip, Wres);                // 2
    k_init<<<NB * TT * NC / 256, 256>>>(x, Wc, bc);                // 3
    k_layer<<<NB * (TT/128), 256, LAYER_SMEM>>>(0, dil[0], bskip, bres); // 4

    // side stream: head-weight conversion + remaining condpre slices
    cudaEventRecord(s_evFork, 0);
    cudaStreamWaitEvent(s_side, s_evFork, 0);
    k_cvtWhead<<<2304, dim3(32, 8), 0, s_side>>>(W1, W2, w1h, w1l, w2h, w2l);
    cudaEventRecord(s_evW, s_side);
    for (int l = 1; l < NL; l++) {
        k_condpre<<<TT/8, 256, 0, s_side>>>(cond, Dt, Ds, Bt, Bs, bt, bs, l);
        cudaEventRecord(s_evL[l], s_side);
    }
    for (int l = 1; l < NL; l++) {
        cudaStreamWaitEvent(0, s_evL[l], 0);
        k_layer<<<NB * (TT/128), 256, LAYER_SMEM>>>(l, dil[l], bskip, bres);
    }

    // heads (gated on head-weight conversion)
    cudaStreamWaitEvent(0, s_evW, 0);
    k_gemm<true><<<dim3(128, 8), 256, GEMM_SMEM>>>(
        skipHi, skipLo, w1h, w1l, b1, o1h, o1l, nullptr, 128, 2048);
    k_gemm<false><<<dim3(128, 1), 256, GEMM_SMEM>>>(
        o1h, o1l, w2h, w2l, b2, nullptr, nullptr, out2p, 2048, 256);

    k_head3<<<NB * TT / 4, 128>>>(W3, b3, out);
}

// round 15
// speedup vs baseline: 1.1615x; 1.1615x over previous
#include <cuda_runtime.h>
#include <cuda_bf16.h>
#include <math.h>
#include <stdint.h>

#define TT    2048
#define NB    8
#define NC    128
#define NCOND 16
#define NL    10

#if defined(__CUDA_ARCH_FEAT_SM103_ALL) || defined(__CUDA_ARCH_FEAT_SM100_ALL) || defined(__CUDA_ARCH_FEAT_SM101_ALL)
#define HAS_TCGEN05 1
#else
#define HAS_TCGEN05 0
#endif

typedef unsigned long long u64;

// ---------------------------------------------------------------------------
// Device scratch
// ---------------------------------------------------------------------------
__device__ float g_h   [NB*TT*NC];
__device__ float g_skip[NB*TT*NC];
__device__ float g_out2[NB*TT*256];
__device__ float g_tcond[(size_t)NL*NB*TT*256];

__device__ __nv_bfloat16 g_hHi  [NB*TT*NC];
__device__ __nv_bfloat16 g_hLo  [NB*TT*NC];
__device__ __nv_bfloat16 g_WgHi [NL*3*256*128];
__device__ __nv_bfloat16 g_WgLo [NL*3*256*128];
__device__ __nv_bfloat16 g_WpHi [NL*256*128];
__device__ __nv_bfloat16 g_WpLo [NL*256*128];

__device__ __nv_bfloat16 g_skipHi[NB*TT*NC];
__device__ __nv_bfloat16 g_skipLo[NB*TT*NC];
__device__ __nv_bfloat16 g_W1tHi [3*2048*128];
__device__ __nv_bfloat16 g_W1tLo [3*2048*128];
__device__ __nv_bfloat16 g_W2tHi [3*256*2048];
__device__ __nv_bfloat16 g_W2tLo [3*256*2048];
__device__ __nv_bfloat16 g_out1Hi[(size_t)NB*TT*2048];
__device__ __nv_bfloat16 g_out1Lo[(size_t)NB*TT*2048];

// ---------------------------------------------------------------------------
// helpers
// ---------------------------------------------------------------------------
__device__ __forceinline__ uint32_t smem_to_u32(const void* p) {
    uint32_t a;
    asm("{ .reg .u64 t; cvta.to.shared.u64 t, %1; cvt.u32.u64 %0, t; }"
        : "=r"(a) : "l"(p));
    return a;
}
__device__ __forceinline__ float rcp_fast(float x) {
    float r; asm("rcp.approx.f32 %0, %1;" : "=f"(r) : "f"(x)); return r;
}
__device__ __forceinline__ float gate_act(float a, float x) {
    a = fminf(fmaxf(a, -15.f), 15.f);
    x = fminf(fmaxf(x, -15.f), 15.f);
    float E = __expf(2.f * a);
    float F = __expf(x);
    float r = rcp_fast((E + 1.f) * (F + 1.f));
    return (E - 1.f) * F * r;
}

#if HAS_TCGEN05
__device__ __forceinline__ uint32_t elect_one_pred() {
    uint32_t pred;
    asm volatile(
        "{\n\t.reg .pred p;\n\telect.sync _|p, 0xFFFFFFFF;\n\t"
        "selp.b32 %0, 1, 0, p;\n\t}" : "=r"(pred));
    return pred;
}

#define TCGEN05_ALLOC(smem_result_addr, nCols) \
    asm volatile("tcgen05.alloc.cta_group::1.sync.aligned.shared::cta.b32 [%0], %1;" \
        :: "r"((uint32_t)(smem_result_addr)), "r"((uint32_t)(nCols)) : "memory")
#define TCGEN05_DEALLOC(tmem_addr, nCols) \
    asm volatile("tcgen05.dealloc.cta_group::1.sync.aligned.b32 %0, %1;" \
        :: "r"(tmem_addr), "r"((uint32_t)(nCols)))
#define TCGEN05_RELINQUISH_ALLOC_PERMIT() \
    asm volatile("tcgen05.relinquish_alloc_permit.cta_group::1.sync.aligned;")
#define TCGEN05_COMMIT(mbar_smem_addr) \
    asm volatile("tcgen05.commit.cta_group::1.mbarrier::arrive::one.shared::cluster.b64 [%0];" \
        :: "r"((uint32_t)(mbar_smem_addr)) : "memory")
#define TCGEN05_FENCE_AFTER() \
    asm volatile("tcgen05.fence::after_thread_sync;" ::: "memory")
#define TCGEN05_WAIT_LD() \
    asm volatile("tcgen05.wait::ld.sync.aligned;" ::: "memory")
#define FENCE_PROXY_ASYNC_SHARED_CTA() \
    asm volatile("fence.proxy.async.shared::cta;" ::: "memory")
#define MBARRIER_INIT(mbar_smem_addr, count) \
    asm volatile("mbarrier.init.shared.b64 [%0], %1;" \
        :: "r"((uint32_t)(mbar_smem_addr)), "r"((uint32_t)(count)) : "memory")

#define MBARRIER_WAIT_PARITY(mbar_smem_addr, phase_parity) do { \
    uint32_t _mbar = (uint32_t)(mbar_smem_addr); \
    uint32_t _parity = (uint32_t)(phase_parity); \
    uint32_t _done; \
    asm volatile( \
        "{\n\t.reg .pred p;\n\t" \
        "mbarrier.try_wait.parity.acquire.cta.shared::cta.b64 p, [%1], %2;\n\t" \
        "selp.b32 %0, 1, 0, p;\n\t}" \
        : "=r"(_done) : "r"(_mbar), "r"(_parity) : "memory"); \
    if (!_done) { \
        asm volatile( \
            "{\n\t.reg .pred P1;\n\t" \
            "WAIT_LOOP_%=:\n\t" \
            "mbarrier.try_wait.parity.acquire.cta.shared::cta.b64 P1, [%0], %1, 0x989680;\n\t" \
            "@P1 bra.uni WAIT_DONE_%=;\n\t" \
            "bra.uni WAIT_LOOP_%=;\n\t" \
            "WAIT_DONE_%=:\n\t}" \
            :: "r"(_mbar), "r"(_parity) : "memory"); \
    } \
} while(0)

#define TCGEN05_LD_32X32B_X32(r, tmem_addr) \
    asm volatile( \
        "tcgen05.ld.sync.aligned.32x32b.x32.b32 " \
        "{%0, %1, %2, %3, %4, %5, %6, %7, " \
        " %8, %9, %10, %11, %12, %13, %14, %15, " \
        " %16, %17, %18, %19, %20, %21, %22, %23, " \
        " %24, %25, %26, %27, %28, %29, %30, %31}, [%32];" \
        : "=r"((r)[0]),  "=r"((r)[1]),  "=r"((r)[2]),  "=r"((r)[3]), \
          "=r"((r)[4]),  "=r"((r)[5]),  "=r"((r)[6]),  "=r"((r)[7]), \
          "=r"((r)[8]),  "=r"((r)[9]),  "=r"((r)[10]), "=r"((r)[11]), \
          "=r"((r)[12]), "=r"((r)[13]), "=r"((r)[14]), "=r"((r)[15]), \
          "=r"((r)[16]), "=r"((r)[17]), "=r"((r)[18]), "=r"((r)[19]), \
          "=r"((r)[20]), "=r"((r)[21]), "=r"((r)[22]), "=r"((r)[23]), \
          "=r"((r)[24]), "=r"((r)[25]), "=r"((r)[26]), "=r"((r)[27]), \
          "=r"((r)[28]), "=r"((r)[29]), "=r"((r)[30]), "=r"((r)[31]) \
        : "r"(tmem_addr))

static constexpr unsigned long long SMEM_DESC_BASE_SW128 =
    (2ull << 61) | (1ull << 46) | (64ull << 32) | (1ull << 16);
#define MAKE_SMEM_DESC(a) (SMEM_DESC_BASE_SW128 | ((unsigned long long)((a) >> 4) & 0x3FFF))

__device__ __forceinline__ void mma_bf16_ss(uint32_t d, u64 ad, u64 bd,
                                            uint32_t idesc, uint32_t en) {
    asm volatile(
        "{\n\t.reg .pred p;\n\t"
        "setp.ne.u32 p, %4, 0;\n\t"
        "tcgen05.mma.cta_group::1.kind::f16 [%0], %1, %2, %3, {%5, %5, %5, %5}, p;\n\t"
        "}"
        :: "r"(d), "l"(ad), "l"(bd), "r"(idesc), "r"(en), "r"(0u)
        : "memory");
}

static constexpr uint32_t GEMM_IDESC =
    (1u << 4) | (1u << 7) | (1u << 10) | ((128u / 8) << 17) | ((128u / 16) << 24);
static constexpr uint32_t IDESC_N256 =
    (1u << 4) | (1u << 7) | (1u << 10) | ((256u / 8) << 17) | ((128u / 16) << 24);
#endif // HAS_TCGEN05

// ---------------------------------------------------------------------------
__global__ __launch_bounds__(256) void k_init(const float* __restrict__ x,
                                              const float* __restrict__ Wc,
                                              const float* __restrict__ bc) {
    int idx = blockIdx.x * 256 + threadIdx.x;
    int c  = idx & (NC - 1);
    int bt = idx >> 7;
    float v = x[bt] * Wc[c] + bc[c];
    g_h[idx]    = v;
    g_skip[idx] = 0.f;
    __nv_bfloat16 h = __float2bfloat16(v);
    g_hHi[idx] = h;
    g_hLo[idx] = __float2bfloat16(v - __bfloat162float(h));
}

// ---------------------------------------------------------------------------
__global__ __launch_bounds__(256) void k_cvtStack(
    const float* __restrict__ Wt, const float* __restrict__ Ws,
    const float* __restrict__ Wskip, const float* __restrict__ Wres)
{
    __shared__ float t[32][33];
    int id = blockIdx.x;
    int tid = threadIdx.x;
    int tx = tid & 31, ty = tid >> 5;

    const float* src;
    __nv_bfloat16 *dhi, *dlo;
    int co0, ci0, gate;
    size_t obase;
    if (id < 960) {
        int z = id / 16, rem = id % 16;
        co0 = (rem & 3) * 32; ci0 = (rem >> 2) * 32;
        int lt = z >> 1; gate = z & 1;
        src = (gate ? Ws : Wt) + (size_t)lt * 128 * 128;
        dhi = g_WgHi; dlo = g_WgLo;
        obase = (size_t)lt * 256 * 128;
    } else {
        int id2 = id - 960;
        int z = id2 / 16, rem = id2 % 16;
        co0 = (rem & 3) * 32; ci0 = (rem >> 2) * 32;
        int l = z >> 1; gate = z & 1;
        src = (gate ? Wres : Wskip) + (size_t)l * 128 * 128;
        dhi = g_WpHi; dlo = g_WpLo;
        obase = (size_t)l * 256 * 128;
    }
    #pragma unroll
    for (int r = 0; r < 4; r++)
        t[ty + r*8][tx] = src[(ci0 + ty + r*8) * 128 + co0 + tx];
    __syncthreads();
    #pragma unroll
    for (int r = 0; r < 4; r++) {
        float v = t[tx][ty + r*8];
        int n = gate * 128 + co0 + ty + r*8;
        size_t o = obase + (size_t)n * 128 + ci0 + tx;
        __nv_bfloat16 h = __float2bfloat16(v);
        dhi[o] = h;
        dlo[o] = __float2bfloat16(v - __bfloat162float(h));
    }
}

__global__ void k_cvtWhead(const float* __restrict__ W1, const float* __restrict__ W2,
                           __nv_bfloat16* __restrict__ w1h, __nv_bfloat16* __restrict__ w1l,
                           __nv_bfloat16* __restrict__ w2h, __nv_bfloat16* __restrict__ w2l) {
    __shared__ float t[32][33];
    int id = blockIdx.x;
    const float* src; __nv_bfloat16 *dhi, *dlo;
    int K, N, n0, k0, tap;
    if (id < 768) {
        tap = id / 256; int rem = id % 256;
        n0 = (rem & 63) * 32; k0 = (rem >> 6) * 32;
        src = W1; dhi = w1h; dlo = w1l; K = 128; N = 2048;
    } else {
        id -= 768;
        tap = id / 512; int rem = id % 512;
        n0 = (rem & 7) * 32; k0 = (rem >> 3) * 32;
        src = W2; dhi = w2h; dlo = w2l; K = 2048; N = 256;
    }
    int tx = threadIdx.x, ty = threadIdx.y;
    #pragma unroll
    for (int r = 0; r < 4; r++)
        t[ty + r*8][tx] = src[((size_t)tap*K + k0 + ty + r*8) * N + n0 + tx];
    __syncthreads();
    #pragma unroll
    for (int r = 0; r < 4; r++) {
        float v = t[tx][ty + r*8];
        __nv_bfloat16 h = __float2bfloat16(v);
        __nv_bfloat16 l = __float2bfloat16(v - __bfloat162float(h));
        size_t o = ((size_t)tap*N + n0 + ty + r*8) * K + k0 + tx;
        dhi[o] = h; dlo[o] = l;
    }
}

// ---------------------------------------------------------------------------
__global__ __launch_bounds__(256) void k_condpre(
    const float* __restrict__ cond,
    const float* __restrict__ Dt, const float* __restrict__ Ds,
    const float* __restrict__ Bt, const float* __restrict__ Bs,
    const float* __restrict__ bt, const float* __restrict__ bs, int l)
{
    const int tid = threadIdx.x;
    const int co = (tid & 31) << 2;
    const int gate = (tid >> 5) & 1;
    const int tq = tid >> 6;
    const int t0 = blockIdx.x * 8 + tq;

    __shared__ float sc[NB][NCOND];
    if (tid < NB * NCOND) sc[tid >> 4][tid & 15] = cond[tid];
    __syncthreads();

    const float* D  = gate ? Ds : Dt;
    const float* Bm = gate ? Bs : Bt;
    float4 bias = *(const float4*)((gate ? bs : bt) + l * 128 + co);

    float4 acc[2][NB];
    #pragma unroll
    for (int tt = 0; tt < 2; tt++)
        #pragma unroll
        for (int b = 0; b < NB; b++) acc[tt][b] = make_float4(0.f, 0.f, 0.f, 0.f);

    #pragma unroll 4
    for (int c = 0; c < NCOND; c++) {
        size_t base = (((size_t)l * NCOND + c) * TT + t0) * 128 + co;
        float4 d0 = *(const float4*)(D + base);
        float4 d1 = *(const float4*)(D + base + 4 * 128);
        #pragma unroll
        for (int b = 0; b < NB; b++) {
            float s = sc[b][c];
            acc[0][b].x = fmaf(s, d0.x, acc[0][b].x);
            acc[0][b].y = fmaf(s, d0.y, acc[0][b].y);
            acc[0][b].z = fmaf(s, d0.z, acc[0][b].z);
            acc[0][b].w = fmaf(s, d0.w, acc[0][b].w);
            acc[1][b].x = fmaf(s, d1.x, acc[1][b].x);
            acc[1][b].y = fmaf(s, d1.y, acc[1][b].y);
            acc[1][b].z = fmaf(s, d1.z, acc[1][b].z);
            acc[1][b].w = fmaf(s, d1.w, acc[1][b].w);
        }
    }
    #pragma unroll
    for (int tt = 0; tt < 2; tt++) {
        int t = t0 + tt * 4;
        float4 bm = *(const float4*)(Bm + ((size_t)l * TT + t) * 128 + co);
        bm.x += bias.x; bm.y += bias.y; bm.z += bias.z; bm.w += bias.w;
        #pragma unroll
        for (int b = 0; b < NB; b++) {
            float4 v = acc[tt][b];
            v.x += bm.x; v.y += bm.y; v.z += bm.z; v.w += bm.w;
            *(float4*)(g_tcond + (((size_t)l * NB + b) * TT + t) * 256
                       + gate * 128 + co) = v;
        }
    }
}

// ---------------------------------------------------------------------------
// Fused residual layer: 512 threads (16 warps) for latency hiding.
// ---------------------------------------------------------------------------
#define LAYER_SMEM 200704

__global__ __launch_bounds__(512, 1) void k_layer(
    int l, int d, const float* __restrict__ bskip, const float* __restrict__ bres)
{
#if HAS_TCGEN05
    extern __shared__ char dsm[];
    const int tid = threadIdx.x;
    const int wid = tid >> 5;
    const int lane = tid & 31;

    uint32_t raw = smem_to_u32(dsm);
    uint32_t abase = (raw + 1023) & ~1023u;
    char* hdr = dsm + (abase - raw);
    char* G   = hdr + 2048;
    const uint32_t hdr_a = abase;
    const uint32_t G_a   = abase + 2048;

    const int b  = blockIdx.x >> 4;
    const int t0 = (blockIdx.x & 15) << 7;

    if (tid == 0) {
        MBARRIER_INIT(hdr_a + 8, 1);
        MBARRIER_INIT(hdr_a + 16, 1);
    }
    if (wid == 0) TCGEN05_ALLOC(hdr_a, 512);
    __syncthreads();

    uint32_t tmem;
    asm volatile("ld.shared.b32 %0, [%1];" : "=r"(tmem) : "r"(hdr_a));

    int phase[2] = {0, 0};

    // ---- gate phase: 6 chunks ----
    for (int ch = 0; ch < 6; ch++) {
        const int buf = ch & 1;
        char* Gb = G + buf * 98304;
        const uint32_t Gb_a = G_a + buf * 98304;
        const int tap = ch >> 1;
        const int ci0 = (ch & 1) << 6;

        // A: thread = (row r4 = tid>>2, quarter qu = tid&3): 1 hi + 1 lo uint4 x2
        uint4 va[4];
        const int r4 = tid >> 2, qu = tid & 3;
        {
            int trow = t0 + r4 + (tap - 1) * d;
            bool ok = (unsigned)trow < (unsigned)TT;
            size_t goff = ((size_t)(b * TT + (ok ? trow : 0))) * NC + ci0 + qu * 16;
            if (ok) {
                va[0] = *(const uint4*)(g_hHi + goff);
                va[1] = *(const uint4*)(g_hHi + goff + 8);
                va[2] = *(const uint4*)(g_hLo + goff);
                va[3] = *(const uint4*)(g_hLo + goff + 8);
            } else {
                va[0] = make_uint4(0,0,0,0); va[1] = make_uint4(0,0,0,0);
                va[2] = make_uint4(0,0,0,0); va[3] = make_uint4(0,0,0,0);
            }
        }
        // B: thread = (row rb = tid>>1, half hb = tid&1): 4 hi + 4 lo uint4
        uint4 wb[8];
        const int rb = tid >> 1, hb = tid & 1;
        {
            size_t woff = (((size_t)(l * 3 + tap)) * 256 + rb) * 128 + ci0 + hb * 32;
            #pragma unroll
            for (int q = 0; q < 4; q++) {
                wb[q]     = *(const uint4*)(g_WgHi + woff + q * 8);
                wb[4 + q] = *(const uint4*)(g_WgLo + woff + q * 8);
            }
        }

        if (ch >= 2) {
            MBARRIER_WAIT_PARITY(hdr_a + 8 + 8 * buf, phase[buf]);
            phase[buf] ^= 1;
        }

        #pragma unroll
        for (int q = 0; q < 2; q++) {
            int c = qu * 2 + q;
            uint32_t so = r4 * 128 + (((uint32_t)(c ^ (r4 & 7))) << 4);
            *(uint4*)(Gb + so)         = va[q];
            *(uint4*)(Gb + 16384 + so) = va[2 + q];
        }
        #pragma unroll
        for (int q = 0; q < 4; q++) {
            int c = hb * 4 + q;
            uint32_t so = rb * 128 + (((uint32_t)(c ^ (rb & 7))) << 4);
            *(uint4*)(Gb + 32768 + so) = wb[q];
            *(uint4*)(Gb + 65536 + so) = wb[4 + q];
        }
        FENCE_PROXY_ASYNC_SHARED_CTA();
        __syncthreads();

        if (wid == 0 && elect_one_pred()) {
            u64 dAh = MAKE_SMEM_DESC(Gb_a);
            u64 dAl = MAKE_SMEM_DESC(Gb_a + 16384);
            u64 dBh = MAKE_SMEM_DESC(Gb_a + 32768);
            u64 dBl = MAKE_SMEM_DESC(Gb_a + 65536);
            uint32_t en = (ch != 0);
            #pragma unroll
            for (int ks = 0; ks < 4; ks++) {
                mma_bf16_ss(tmem, dAh + 2*ks, dBh + 2*ks, IDESC_N256, en); en = 1;
                mma_bf16_ss(tmem, dAh + 2*ks, dBl + 2*ks, IDESC_N256, 1);
                mma_bf16_ss(tmem, dAl + 2*ks, dBh + 2*ks, IDESC_N256, 1);
            }
            TCGEN05_COMMIT(hdr_a + 8 + 8 * buf);
        }
    }

    MBARRIER_WAIT_PARITY(hdr_a + 8,  phase[0]);
    MBARRIER_WAIT_PARITY(hdr_a + 16, phase[1]);
    const int postPh = phase[0] ^ 1;
    TCGEN05_FENCE_AFTER();
    __syncthreads();

    // ---- stage tcond coalesced into smem [t 128][260 f] ----
    float* tcS = (float*)(G + 65536);
    {
        const float* tcg = g_tcond + (((size_t)l * NB + b) * TT + t0) * 256;
        #pragma unroll
        for (int k = 0; k < 16; k++) {
            int i4 = tid + k * 512;
            int row = i4 >> 6, c4 = (i4 & 63) << 2;
            float4 v = *(const float4*)(tcg + (size_t)row * 256 + c4);
            *(float4*)(tcS + row * 260 + c4) = v;
        }
    }
    __syncthreads();

    // ---- epilogue 1 (16 warps: rows (wid&3)*32, cols (wid>>2)*32) ----
    {
        const int row = (wid & 3) * 32 + lane;
        const int c0 = (wid >> 2) * 32;
        const float* trow_ = tcS + row * 260;
        uint32_t rt[32], rs[32];
        TCGEN05_LD_32X32B_X32(rt, tmem + c0);
        TCGEN05_LD_32X32B_X32(rs, tmem + 128 + c0);
        TCGEN05_WAIT_LD();
        #pragma unroll
        for (int j = 0; j < 32; j += 4) {
            int c = c0 + j;
            float4 ta = *(const float4*)(trow_ + c);
            float4 tx = *(const float4*)(trow_ + 128 + c);
            float av[4] = {__uint_as_float(rt[j])   + ta.x,
                           __uint_as_float(rt[j+1]) + ta.y,
                           __uint_as_float(rt[j+2]) + ta.z,
                           __uint_as_float(rt[j+3]) + ta.w};
            float xv[4] = {__uint_as_float(rs[j])   + tx.x,
                           __uint_as_float(rs[j+1]) + tx.y,
                           __uint_as_float(rs[j+2]) + tx.z,
                           __uint_as_float(rs[j+3]) + tx.w};
            __nv_bfloat16 hv[4], lv[4];
            #pragma unroll
            for (int q = 0; q < 4; q++) {
                float gv = gate_act(av[q], xv[q]);
                hv[q] = __float2bfloat16(gv);
                lv[q] = __float2bfloat16(gv - __bfloat162float(hv[q]));
            }
            uint32_t off = row * 128 + (c & 63) * 2;
            off ^= (off >> 3) & 0x70;
            char* atp = G + ((c >> 6) * 32768);
            *(uint2*)(atp + off)         = *(const uint2*)hv;
            *(uint2*)(atp + 16384 + off) = *(const uint2*)lv;
        }
    }
    __syncthreads();

    // ---- post weights into G+65536..196608 ----
    {
        const int r = tid >> 1, hb2 = tid & 1;
        size_t woff = ((size_t)l * 256 + r) * 128;
        #pragma unroll
        for (int cc = 0; cc < 2; cc++) {
            char* dst = G + 65536 + cc * 65536;
            #pragma unroll
            for (int q = 0; q < 4; q++) {
                int c = hb2 * 4 + q;
                uint32_t so = r * 128 + (((uint32_t)(c ^ (r & 7))) << 4);
                *(uint4*)(dst + so)         = *(const uint4*)(g_WpHi + woff + cc*64 + c*8);
                *(uint4*)(dst + 32768 + so) = *(const uint4*)(g_WpLo + woff + cc*64 + c*8);
            }
        }
    }
    FENCE_PROXY_ASYNC_SHARED_CTA();
    __syncthreads();

    // ---- post MMA -> tmem cols 256..511 ----
    if (wid == 0 && elect_one_pred()) {
        uint32_t en = 0;
        #pragma unroll
        for (int cc = 0; cc < 2; cc++) {
            u64 dAh = MAKE_SMEM_DESC(G_a + cc * 32768);
            u64 dAl = MAKE_SMEM_DESC(G_a + cc * 32768 + 16384);
            u64 dBh = MAKE_SMEM_DESC(G_a + 65536 + cc * 65536);
            u64 dBl = MAKE_SMEM_DESC(G_a + 65536 + cc * 65536 + 32768);
            #pragma unroll
            for (int ks = 0; ks < 4; ks++) {
                mma_bf16_ss(tmem + 256, dAh + 2*ks, dBh + 2*ks, IDESC_N256, en); en = 1;
                mma_bf16_ss(tmem + 256, dAh + 2*ks, dBl + 2*ks, IDESC_N256, 1);
                mma_bf16_ss(tmem + 256, dAl + 2*ks, dBh + 2*ks, IDESC_N256, 1);
            }
        }
        TCGEN05_COMMIT(hdr_a + 8);
    }
    MBARRIER_WAIT_PARITY(hdr_a + 8, postPh);
    TCGEN05_FENCE_AFTER();
    __syncthreads();

    // ---- epilogue 2a (16 warps): stage D2 into smem [row][260 f] ----
    float* st = (float*)G;
    {
        const int row = (wid & 3) * 32 + lane;
        const int c0 = (wid >> 2) * 64;
        uint32_t ra[32], rb2[32];
        TCGEN05_LD_32X32B_X32(ra,  tmem + 256 + c0);
        TCGEN05_LD_32X32B_X32(rb2, tmem + 256 + c0 + 32);
        TCGEN05_WAIT_LD();
        #pragma unroll
        for (int j = 0; j < 32; j += 4) {
            float4 v1 = make_float4(__uint_as_float(ra[j]),   __uint_as_float(ra[j+1]),
                                    __uint_as_float(ra[j+2]), __uint_as_float(ra[j+3]));
            float4 v2 = make_float4(__uint_as_float(rb2[j]),   __uint_as_float(rb2[j+1]),
                                    __uint_as_float(rb2[j+2]), __uint_as_float(rb2[j+3]));
            *(float4*)(st + row * 260 + c0 + j)      = v1;
            *(float4*)(st + row * 260 + c0 + 32 + j) = v2;
        }
    }
    __syncthreads();

    // ---- epilogue 2b: coalesced RMW of skip/h; last layer -> skip split ----
    {
        const size_t gbase = ((size_t)(b * TT + t0)) * NC;
        const bool lastL = (l == NL - 1);
        #pragma unroll
        for (int k = 0; k < 8; k++) {
            int e = tid + k * 512;
            int row = e >> 5, c4 = (e & 31) << 2;
            float4 dsk = *(const float4*)(st + row * 260 + c4);
            float4 bk4 = *(const float4*)(bskip + l * 128 + c4);
            size_t go = gbase + (size_t)row * NC + c4;
            float4 sk = *(const float4*)(g_skip + go);
            sk.x += dsk.x + bk4.x; sk.y += dsk.y + bk4.y;
            sk.z += dsk.z + bk4.z; sk.w += dsk.w + bk4.w;
            if (!lastL) {
                float4 dre = *(const float4*)(st + row * 260 + 128 + c4);
                float4 br4 = *(const float4*)(bres  + l * 128 + c4);
                float4 hh = *(const float4*)(g_h + go);
                hh.x += dre.x + br4.x; hh.y += dre.y + br4.y;
                hh.z += dre.z + br4.z; hh.w += dre.w + br4.w;
                *(float4*)(g_skip + go) = sk;
                *(float4*)(g_h + go) = hh;
                float hq[4] = {hh.x, hh.y, hh.z, hh.w};
                __nv_bfloat16 hv[4], lv[4];
                #pragma unroll
                for (int q = 0; q < 4; q++) {
                    hv[q] = __float2bfloat16(hq[q]);
                    lv[q] = __float2bfloat16(hq[q] - __bfloat162float(hv[q]));
                }
                *(uint2*)(g_hHi + go) = *(const uint2*)hv;
                *(uint2*)(g_hLo + go) = *(const uint2*)lv;
            } else {
                float sq[4] = {sk.x, sk.y, sk.z, sk.w};
                __nv_bfloat16 hv[4], lv[4];
                #pragma unroll
                for (int q = 0; q < 4; q++) {
                    hv[q] = __float2bfloat16(sq[q]);
                    lv[q] = __float2bfloat16(sq[q] - __bfloat162float(hv[q]));
                }
                *(uint2*)(g_skipHi + go) = *(const uint2*)hv;
                *(uint2*)(g_skipLo + go) = *(const uint2*)lv;
            }
        }
    }
    __syncthreads();
    if (wid == 0) {
        TCGEN05_RELINQUISH_ALLOC_PERMIT();
        TCGEN05_DEALLOC(tmem, 512);
    }
#endif // HAS_TCGEN05
}

// ---------------------------------------------------------------------------
// Head GEMM-conv3, TWO N-tiles per CTA (round-13 validated, unchanged).
// ---------------------------------------------------------------------------
#define GEMM_SMEM 200704

template<bool WB16>
__global__ __launch_bounds__(256, 1) void k_gemm(
    const __nv_bfloat16* __restrict__ aHi, const __nv_bfloat16* __restrict__ aLo,
    const __nv_bfloat16* __restrict__ wHi, const __nv_bfloat16* __restrict__ wLo,
    const float* __restrict__ bias,
    __nv_bfloat16* __restrict__ oHi, __nv_bfloat16* __restrict__ oLo,
    float* __restrict__ oF, int Cin, int CO)
{
#if HAS_TCGEN05
    extern __shared__ char dsm[];
    const int tid = threadIdx.x;
    const int wid = tid >> 5;
    const int lane = tid & 31;

    uint32_t raw = smem_to_u32(dsm);
    uint32_t abase = (raw + 1023) & ~1023u;
    char* hdr   = dsm + (abase - raw);
    char* G     = hdr + 2048;
    const uint32_t hdr_a = abase;
    const uint32_t G_a   = abase + 2048;
    float* sbias = (float*)(hdr + 1024);

    const int b  = blockIdx.x >> 4;
    const int t0 = (blockIdx.x & 15) * 128;
    const int n0 = blockIdx.y * 256;

    if (tid == 0) {
        MBARRIER_INIT(hdr_a + 8, 1);
        MBARRIER_INIT(hdr_a + 16, 1);
    }
    if (wid == 0) TCGEN05_ALLOC(hdr_a, 256);
    sbias[tid] = bias[n0 + tid];
    __syncthreads();

    uint32_t tmem;
    asm volatile("ld.shared.b32 %0, [%1];" : "=r"(tmem) : "r"(hdr_a));

    const int nci = Cin >> 6;
    const int nchunks = 3 * nci;
    const size_t aBatch = (size_t)b * TT * Cin;

    int phase[2] = {0, 0};

    for (int ch = 0; ch < nchunks; ch++) {
        const int buf = ch & 1;
        char* tb = G + buf * 98304;
        const uint32_t tb_a = G_a + buf * 98304;

        const int tap = ch / nci;
        const int ci0 = (ch - tap * nci) << 6;
        const size_t bBase0 = ((size_t)tap * CO + n0) * Cin + ci0;
        const int c = tid & 7;

        uint4 va[8], vb0[8];
        #pragma unroll
        for (int p = 0; p < 4; p++) {
            int r = p * 32 + (tid >> 3);
            int trow = t0 + r + tap - 1;
            if ((unsigned)trow < (unsigned)TT) {
                size_t off = aBatch + (size_t)trow * Cin + ci0 + c * 8;
                va[p]     = *(const uint4*)(aHi + off);
                va[4 + p] = *(const uint4*)(aLo + off);
            } else {
                va[p] = make_uint4(0,0,0,0);
                va[4 + p] = make_uint4(0,0,0,0);
            }
            size_t bo = bBase0 + (size_t)r * Cin + c * 8;
            vb0[p]     = *(const uint4*)(wHi + bo);
            vb0[4 + p] = *(const uint4*)(wLo + bo);
        }

        if (ch >= 2) {
            MBARRIER_WAIT_PARITY(hdr_a + 8 + 8 * buf, phase[buf]);
            phase[buf] ^= 1;
        }

        #pragma unroll
        for (int p = 0; p < 4; p++) {
            int r = p * 32 + (tid >> 3);
            uint32_t so = r * 128 + (((uint32_t)(c ^ (r & 7))) << 4);
            *(uint4*)(tb + so)         = va[p];
            *(uint4*)(tb + 16384 + so) = va[4 + p];
            *(uint4*)(tb + 32768 + so) = vb0[p];
            *(uint4*)(tb + 49152 + so) = vb0[4 + p];
        }
        {
            const size_t bBase1 = bBase0 + (size_t)128 * Cin;
            #pragma unroll
            for (int p = 0; p < 4; p++) {
                int r = p * 32 + (tid >> 3);
                size_t bo = bBase1 + (size_t)r * Cin + c * 8;
                uint4 h4 = *(const uint4*)(wHi + bo);
                uint4 l4 = *(const uint4*)(wLo + bo);
                uint32_t so = r * 128 + (((uint32_t)(c ^ (r & 7))) << 4);
                *(uint4*)(tb + 65536 + so) = h4;
                *(uint4*)(tb + 81920 + so) = l4;
            }
        }
        FENCE_PROXY_ASYNC_SHARED_CTA();
        __syncthreads();

        if (wid == 0 && elect_one_pred()) {
            u64 dAh  = MAKE_SMEM_DESC(tb_a);
            u64 dAl  = MAKE_SMEM_DESC(tb_a + 16384);
            u64 dB0h = MAKE_SMEM_DESC(tb_a + 32768);
            u64 dB0l = MAKE_SMEM_DESC(tb_a + 49152);
            u64 dB1h = MAKE_SMEM_DESC(tb_a + 65536);
            u64 dB1l = MAKE_SMEM_DESC(tb_a + 81920);
            uint32_t en = (ch != 0);
            #pragma unroll
            for (int ks = 0; ks < 4; ks++) {
                mma_bf16_ss(tmem,       dAh + 2*ks, dB0h + 2*ks, GEMM_IDESC, en);
                mma_bf16_ss(tmem + 128, dAh + 2*ks, dB1h + 2*ks, GEMM_IDESC, en);
                en = 1;
                mma_bf16_ss(tmem,       dAh + 2*ks, dB0l + 2*ks, GEMM_IDESC, 1);
                mma_bf16_ss(tmem,       dAl + 2*ks, dB0h + 2*ks, GEMM_IDESC, 1);
                mma_bf16_ss(tmem + 128, dAh + 2*ks, dB1l + 2*ks, GEMM_IDESC, 1);
                mma_bf16_ss(tmem + 128, dAl + 2*ks, dB1h + 2*ks, GEMM_IDESC, 1);
            }
            TCGEN05_COMMIT(hdr_a + 8 + 8 * buf);
        }
    }

    MBARRIER_WAIT_PARITY(hdr_a + 8,  phase[0]);
    MBARRIER_WAIT_PARITY(hdr_a + 16, phase[1]);
    TCGEN05_FENCE_AFTER();
    __syncthreads();

    #pragma unroll 1
    for (int nt = 0; nt < 2; nt++) {
        const uint32_t dbase = tmem + nt * 128;
        const int nb = n0 + nt * 128;
        if (WB16) {
            char* hiS = G;
            char* loS = G + 34816;
            {
                const int m = (wid & 3) * 32 + lane;
                const int cg = (wid >> 2) * 64;
                #pragma unroll 1
                for (int half2 = 0; half2 < 2; half2++) {
                    int c0 = cg + half2 * 32;
                    uint32_t r32[32];
                    TCGEN05_LD_32X32B_X32(r32, dbase + c0);
                    TCGEN05_WAIT_LD();
                    #pragma unroll
                    for (int j = 0; j < 32; j += 2) {
                        __nv_bfloat16 hv[2], lv[2];
                        #pragma unroll
                        for (int q = 0; q < 2; q++) {
                            float v = __uint_as_float(r32[j+q]) + sbias[nt*128 + c0 + j + q];
                            v = fmaxf(v, 0.f);
                            hv[q] = __float2bfloat16(v);
                            lv[q] = __float2bfloat16(v - __bfloat162float(hv[q]));
                        }
                        uint32_t so = m * 272 + (c0 + j) * 2;
                        *(uint32_t*)(hiS + so) = *(const uint32_t*)hv;
                        *(uint32_t*)(loS + so) = *(const uint32_t*)lv;
                    }
                }
            }
            __syncthreads();
            #pragma unroll
            for (int k = 0; k < 8; k++) {
                int e = tid + k * 256;
                int row = e >> 4, cu = e & 15;
                uint4 h4 = *(const uint4*)(hiS + row * 272 + cu * 16);
                uint4 l4 = *(const uint4*)(loS + row * 272 + cu * 16);
                size_t o = (size_t)(b * TT + t0 + row) * CO + nb + cu * 8;
                *(uint4*)(oHi + o) = h4;
                *(uint4*)(oLo + o) = l4;
            }
            __syncthreads();
        } else {
            float* fS = (float*)G;
            {
                const int m = (wid & 3) * 32 + lane;
                const int cg = (wid >> 2) * 64;
                #pragma unroll 1
                for (int half2 = 0; half2 < 2; half2++) {
                    int c0 = cg + half2 * 32;
                    uint32_t r32[32];
                    TCGEN05_LD_32X32B_X32(r32, dbase + c0);
                    TCGEN05_WAIT_LD();
                    #pragma unroll
                    for (int j = 0; j < 32; j += 4) {
                        float4 v;
                        v.x = fmaxf(__uint_as_float(r32[j])   + sbias[nt*128 + c0+j],   0.f);
                        v.y = fmaxf(__uint_as_float(r32[j+1]) + sbias[nt*128 + c0+j+1], 0.f);
                        v.z = fmaxf(__uint_as_float(r32[j+2]) + sbias[nt*128 + c0+j+2], 0.f);
                        v.w = fmaxf(__uint_as_float(r32[j+3]) + sbias[nt*128 + c0+j+3], 0.f);
                        *(float4*)(fS + m * 132 + c0 + j) = v;
                    }
                }
            }
            __syncthreads();
            #pragma unroll
            for (int k = 0; k < 16; k++) {
                int e = tid + k * 256;
                int row = e >> 5, c4 = (e & 31) << 2;
                float4 v = *(const float4*)(fS + row * 132 + c4);
                *(float4*)(oF + (size_t)(b * TT + t0 + row) * CO + nb + c4) = v;
            }
            __syncthreads();
        }
    }

    if (wid == 0) {
        TCGEN05_RELINQUISH_ALLOC_PERMIT();
        TCGEN05_DEALLOC(tmem, 256);
    }
#endif // HAS_TCGEN05
}

// ---------------------------------------------------------------------------
__global__ __launch_bounds__(128) void k_head3(const float* __restrict__ W3,
                                               const float* __restrict__ b3,
                                               float* __restrict__ out)
{
    int row  = blockIdx.x * 4 + (threadIdx.x >> 5);
    int lane = threadIdx.x & 31;
    const float* p = g_out2 + (size_t)row * 256;
    float s = 0.f;
    #pragma unroll
    for (int i = 0; i < 8; i++) s = fmaf(p[lane + 32 * i], W3[lane + 32 * i], s);
    #pragma unroll
    for (int o = 16; o; o >>= 1) s += __shfl_xor_sync(0xffffffffu, s, o);
    if (lane == 0) out[row] = tanhf(s + b3[0]);
}

// ---------------------------------------------------------------------------
static cudaStream_t s_side = nullptr;
static cudaEvent_t  s_evFork = nullptr;
static cudaEvent_t  s_evW = nullptr;
static cudaEvent_t  s_evL[NL];

extern "C" void kernel_launch(void* const* d_in, const int* in_sizes, int n_in,
                              void* d_out, int out_size) {
    const float* x     = (const float*)d_in[0];
    const float* cond  = (const float*)d_in[1];
    const float* Wc    = (const float*)d_in[2];
    const float* bc    = (const float*)d_in[3];
    const float* Wt    = (const float*)d_in[4];
    const float* bt    = (const float*)d_in[5];
    const float* Ws    = (const float*)d_in[6];
    const float* bs    = (const float*)d_in[7];
    const float* Dt    = (const float*)d_in[8];
    const float* Bt    = (const float*)d_in[9];
    const float* Ds    = (const float*)d_in[10];
    const float* Bs    = (const float*)d_in[11];
    const float* Wskip = (const float*)d_in[12];
    const float* bskip = (const float*)d_in[13];
    const float* Wres  = (const float*)d_in[14];
    const float* bres  = (const float*)d_in[15];
    const float* W1    = (const float*)d_in[16];
    const float* b1    = (const float*)d_in[17];
    const float* W2    = (const float*)d_in[18];
    const float* b2    = (const float*)d_in[19];
    const float* W3    = (const float*)d_in[20];
    const float* b3    = (const float*)d_in[21];
    float* out = (float*)d_out;

    if (!s_side) {
        cudaStreamCreateWithFlags(&s_side, cudaStreamNonBlocking);
        cudaEventCreateWithFlags(&s_evFork, cudaEventDisableTiming);
        cudaEventCreateWithFlags(&s_evW, cudaEventDisableTiming);
        for (int l = 0; l < NL; l++)
            cudaEventCreateWithFlags(&s_evL[l], cudaEventDisableTiming);
    }

    cudaFuncSetAttribute(k_layer, cudaFuncAttributeMaxDynamicSharedMemorySize, LAYER_SMEM);
    cudaFuncSetAttribute(k_gemm<true>,  cudaFuncAttributeMaxDynamicSharedMemorySize, GEMM_SMEM);
    cudaFuncSetAttribute(k_gemm<false>, cudaFuncAttributeMaxDynamicSharedMemorySize, GEMM_SMEM);

    __nv_bfloat16 *skipHi, *skipLo, *w1h, *w1l, *w2h, *w2l, *o1h, *o1l;
    float* out2p;
    cudaGetSymbolAddress((void**)&skipHi, g_skipHi);
    cudaGetSymbolAddress((void**)&skipLo, g_skipLo);
    cudaGetSymbolAddress((void**)&w1h, g_W1tHi);
    cudaGetSymbolAddress((void**)&w1l, g_W1tLo);
    cudaGetSymbolAddress((void**)&w2h, g_W2tHi);
    cudaGetSymbolAddress((void**)&w2l, g_W2tLo);
    cudaGetSymbolAddress((void**)&o1h, g_out1Hi);
    cudaGetSymbolAddress((void**)&o1l, g_out1Lo);
    cudaGetSymbolAddress((void**)&out2p, g_out2);

    const int dil[NL] = {1, 2, 4, 8, 16, 32, 64, 128, 256, 512};

    // main stream; k_layer(0) is the 4th launch (ncu profiles the 4th)
    k_condpre<<<TT/8, 256>>>(cond, Dt, Ds, Bt, Bs, bt, bs, 0);     // 1
    k_cvtStack<<<1280, 256>>>(Wt, Ws, Wskip, Wres);                // 2
    k_init<<<NB * TT * NC / 256, 256>>>(x, Wc, bc);                // 3
    k_layer<<<NB * (TT/128), 512, LAYER_SMEM>>>(0, dil[0], bskip, bres); // 4

    // side stream: head-weight conversion + remaining condpre slices
    cudaEventRecord(s_evFork, 0);
    cudaStreamWaitEvent(s_side, s_evFork, 0);
    k_cvtWhead<<<2304, dim3(32, 8), 0, s_side>>>(W1, W2, w1h, w1l, w2h, w2l);
    cudaEventRecord(s_evW, s_side);
    for (int l = 1; l < NL; l++) {
        k_condpre<<<TT/8, 256, 0, s_side>>>(cond, Dt, Ds, Bt, Bs, bt, bs, l);
        cudaEventRecord(s_evL[l], s_side);
    }
    for (int l = 1; l < NL; l++) {
        cudaStreamWaitEvent(0, s_evL[l], 0);
        k_layer<<<NB * (TT/128), 512, LAYER_SMEM>>>(l, dil[l], bskip, bres);
    }

    // heads (gated on head-weight conversion)
    cudaStreamWaitEvent(0, s_evW, 0);
    k_gemm<true><<<dim3(128, 8), 256, GEMM_SMEM>>>(
        skipHi, skipLo, w1h, w1l, b1, o1h, o1l, nullptr, 128, 2048);
    k_gemm<false><<<dim3(128, 1), 256, GEMM_SMEM>>>(
        o1h, o1l, w2h, w2l, b2, nullptr, nullptr, out2p, 2048, 256);

    k_head3<<<NB * TT / 4, 128>>>(W3, b3, out);
}

// round 16
// speedup vs baseline: 1.2763x; 1.0988x over previous
#include <cuda_runtime.h>
#include <cuda_bf16.h>
#include <math.h>
#include <stdint.h>

#define TT    2048
#define NB    8
#define NC    128
#define NCOND 16
#define NL    10

#if defined(__CUDA_ARCH_FEAT_SM103_ALL) || defined(__CUDA_ARCH_FEAT_SM100_ALL) || defined(__CUDA_ARCH_FEAT_SM101_ALL)
#define HAS_TCGEN05 1
#else
#define HAS_TCGEN05 0
#endif

typedef unsigned long long u64;

// ---------------------------------------------------------------------------
// Device scratch
// ---------------------------------------------------------------------------
__device__ float g_h   [NB*TT*NC];
__device__ float g_skip[NB*TT*NC];
__device__ float g_out2[NB*TT*256];
__device__ float g_tcond[(size_t)NL*NB*TT*256];

__device__ __nv_bfloat16 g_hHi  [NB*TT*NC];
__device__ __nv_bfloat16 g_hLo  [NB*TT*NC];
__device__ __nv_bfloat16 g_WgHi [NL*3*256*128];
__device__ __nv_bfloat16 g_WgLo [NL*3*256*128];
__device__ __nv_bfloat16 g_WpHi [NL*256*128];
__device__ __nv_bfloat16 g_WpLo [NL*256*128];

__device__ __nv_bfloat16 g_skipHi[NB*TT*NC];
__device__ __nv_bfloat16 g_skipLo[NB*TT*NC];
__device__ __nv_bfloat16 g_W1tHi [3*2048*128];
__device__ __nv_bfloat16 g_W1tLo [3*2048*128];
__device__ __nv_bfloat16 g_W2tHi [3*256*2048];
__device__ __nv_bfloat16 g_W2tLo [3*256*2048];
__device__ __nv_bfloat16 g_out1Hi[(size_t)NB*TT*2048];
__device__ __nv_bfloat16 g_out1Lo[(size_t)NB*TT*2048];

// ---------------------------------------------------------------------------
// helpers
// ---------------------------------------------------------------------------
__device__ __forceinline__ uint32_t smem_to_u32(const void* p) {
    uint32_t a;
    asm("{ .reg .u64 t; cvta.to.shared.u64 t, %1; cvt.u32.u64 %0, t; }"
        : "=r"(a) : "l"(p));
    return a;
}
__device__ __forceinline__ float rcp_fast(float x) {
    float r; asm("rcp.approx.f32 %0, %1;" : "=f"(r) : "f"(x)); return r;
}
__device__ __forceinline__ float gate_act(float a, float x) {
    a = fminf(fmaxf(a, -15.f), 15.f);
    x = fminf(fmaxf(x, -15.f), 15.f);
    float E = __expf(2.f * a);
    float F = __expf(x);
    float r = rcp_fast((E + 1.f) * (F + 1.f));
    return (E - 1.f) * F * r;
}

#if HAS_TCGEN05
__device__ __forceinline__ uint32_t elect_one_pred() {
    uint32_t pred;
    asm volatile(
        "{\n\t.reg .pred p;\n\telect.sync _|p, 0xFFFFFFFF;\n\t"
        "selp.b32 %0, 1, 0, p;\n\t}" : "=r"(pred));
    return pred;
}

#define TCGEN05_ALLOC(smem_result_addr, nCols) \
    asm volatile("tcgen05.alloc.cta_group::1.sync.aligned.shared::cta.b32 [%0], %1;" \
        :: "r"((uint32_t)(smem_result_addr)), "r"((uint32_t)(nCols)) : "memory")
#define TCGEN05_DEALLOC(tmem_addr, nCols) \
    asm volatile("tcgen05.dealloc.cta_group::1.sync.aligned.b32 %0, %1;" \
        :: "r"(tmem_addr), "r"((uint32_t)(nCols)))
#define TCGEN05_RELINQUISH_ALLOC_PERMIT() \
    asm volatile("tcgen05.relinquish_alloc_permit.cta_group::1.sync.aligned;")
#define TCGEN05_COMMIT(mbar_smem_addr) \
    asm volatile("tcgen05.commit.cta_group::1.mbarrier::arrive::one.shared::cluster.b64 [%0];" \
        :: "r"((uint32_t)(mbar_smem_addr)) : "memory")
#define TCGEN05_FENCE_AFTER() \
    asm volatile("tcgen05.fence::after_thread_sync;" ::: "memory")
#define TCGEN05_WAIT_LD() \
    asm volatile("tcgen05.wait::ld.sync.aligned;" ::: "memory")
#define FENCE_PROXY_ASYNC_SHARED_CTA() \
    asm volatile("fence.proxy.async.shared::cta;" ::: "memory")
#define MBARRIER_INIT(mbar_smem_addr, count) \
    asm volatile("mbarrier.init.shared.b64 [%0], %1;" \
        :: "r"((uint32_t)(mbar_smem_addr)), "r"((uint32_t)(count)) : "memory")

#define MBARRIER_WAIT_PARITY(mbar_smem_addr, phase_parity) do { \
    uint32_t _mbar = (uint32_t)(mbar_smem_addr); \
    uint32_t _parity = (uint32_t)(phase_parity); \
    uint32_t _done; \
    asm volatile( \
        "{\n\t.reg .pred p;\n\t" \
        "mbarrier.try_wait.parity.acquire.cta.shared::cta.b64 p, [%1], %2;\n\t" \
        "selp.b32 %0, 1, 0, p;\n\t}" \
        : "=r"(_done) : "r"(_mbar), "r"(_parity) : "memory"); \
    if (!_done) { \
        asm volatile( \
            "{\n\t.reg .pred P1;\n\t" \
            "WAIT_LOOP_%=:\n\t" \
            "mbarrier.try_wait.parity.acquire.cta.shared::cta.b64 P1, [%0], %1, 0x989680;\n\t" \
            "@P1 bra.uni WAIT_DONE_%=;\n\t" \
            "bra.uni WAIT_LOOP_%=;\n\t" \
            "WAIT_DONE_%=:\n\t}" \
            :: "r"(_mbar), "r"(_parity) : "memory"); \
    } \
} while(0)

#define TCGEN05_LD_32X32B_X32(r, tmem_addr) \
    asm volatile( \
        "tcgen05.ld.sync.aligned.32x32b.x32.b32 " \
        "{%0, %1, %2, %3, %4, %5, %6, %7, " \
        " %8, %9, %10, %11, %12, %13, %14, %15, " \
        " %16, %17, %18, %19, %20, %21, %22, %23, " \
        " %24, %25, %26, %27, %28, %29, %30, %31}, [%32];" \
        : "=r"((r)[0]),  "=r"((r)[1]),  "=r"((r)[2]),  "=r"((r)[3]), \
          "=r"((r)[4]),  "=r"((r)[5]),  "=r"((r)[6]),  "=r"((r)[7]), \
          "=r"((r)[8]),  "=r"((r)[9]),  "=r"((r)[10]), "=r"((r)[11]), \
          "=r"((r)[12]), "=r"((r)[13]), "=r"((r)[14]), "=r"((r)[15]), \
          "=r"((r)[16]), "=r"((r)[17]), "=r"((r)[18]), "=r"((r)[19]), \
          "=r"((r)[20]), "=r"((r)[21]), "=r"((r)[22]), "=r"((r)[23]), \
          "=r"((r)[24]), "=r"((r)[25]), "=r"((r)[26]), "=r"((r)[27]), \
          "=r"((r)[28]), "=r"((r)[29]), "=r"((r)[30]), "=r"((r)[31]) \
        : "r"(tmem_addr))

#define TCGEN05_LD_32X32B_X16(r, tmem_addr) \
    asm volatile( \
        "tcgen05.ld.sync.aligned.32x32b.x16.b32 " \
        "{%0, %1, %2, %3, %4, %5, %6, %7, " \
        " %8, %9, %10, %11, %12, %13, %14, %15}, [%16];" \
        : "=r"((r)[0]),  "=r"((r)[1]),  "=r"((r)[2]),  "=r"((r)[3]), \
          "=r"((r)[4]),  "=r"((r)[5]),  "=r"((r)[6]),  "=r"((r)[7]), \
          "=r"((r)[8]),  "=r"((r)[9]),  "=r"((r)[10]), "=r"((r)[11]), \
          "=r"((r)[12]), "=r"((r)[13]), "=r"((r)[14]), "=r"((r)[15]) \
        : "r"(tmem_addr))

static constexpr unsigned long long SMEM_DESC_BASE_SW128 =
    (2ull << 61) | (1ull << 46) | (64ull << 32) | (1ull << 16);
#define MAKE_SMEM_DESC(a) (SMEM_DESC_BASE_SW128 | ((unsigned long long)((a) >> 4) & 0x3FFF))

__device__ __forceinline__ void mma_bf16_ss(uint32_t d, u64 ad, u64 bd,
                                            uint32_t idesc, uint32_t en) {
    asm volatile(
        "{\n\t.reg .pred p;\n\t"
        "setp.ne.u32 p, %4, 0;\n\t"
        "tcgen05.mma.cta_group::1.kind::f16 [%0], %1, %2, %3, {%5, %5, %5, %5}, p;\n\t"
        "}"
        :: "r"(d), "l"(ad), "l"(bd), "r"(idesc), "r"(en), "r"(0u)
        : "memory");
}

static constexpr uint32_t GEMM_IDESC =
    (1u << 4) | (1u << 7) | (1u << 10) | ((128u / 8) << 17) | ((128u / 16) << 24);
static constexpr uint32_t IDESC_N256 =
    (1u << 4) | (1u << 7) | (1u << 10) | ((256u / 8) << 17) | ((128u / 16) << 24);
#endif // HAS_TCGEN05

// ---------------------------------------------------------------------------
__global__ __launch_bounds__(256) void k_init(const float* __restrict__ x,
                                              const float* __restrict__ Wc,
                                              const float* __restrict__ bc) {
    int idx = blockIdx.x * 256 + threadIdx.x;
    int c  = idx & (NC - 1);
    int bt = idx >> 7;
    float v = x[bt] * Wc[c] + bc[c];
    g_h[idx]    = v;
    g_skip[idx] = 0.f;
    __nv_bfloat16 h = __float2bfloat16(v);
    g_hHi[idx] = h;
    g_hLo[idx] = __float2bfloat16(v - __bfloat162float(h));
}

// ---------------------------------------------------------------------------
__global__ __launch_bounds__(256) void k_cvtStack(
    const float* __restrict__ Wt, const float* __restrict__ Ws,
    const float* __restrict__ Wskip, const float* __restrict__ Wres)
{
    __shared__ float t[32][33];
    int id = blockIdx.x;
    int tid = threadIdx.x;
    int tx = tid & 31, ty = tid >> 5;

    const float* src;
    __nv_bfloat16 *dhi, *dlo;
    int co0, ci0, gate;
    size_t obase;
    if (id < 960) {
        int z = id / 16, rem = id % 16;
        co0 = (rem & 3) * 32; ci0 = (rem >> 2) * 32;
        int lt = z >> 1; gate = z & 1;
        src = (gate ? Ws : Wt) + (size_t)lt * 128 * 128;
        dhi = g_WgHi; dlo = g_WgLo;
        obase = (size_t)lt * 256 * 128;
    } else {
        int id2 = id - 960;
        int z = id2 / 16, rem = id2 % 16;
        co0 = (rem & 3) * 32; ci0 = (rem >> 2) * 32;
        int l = z >> 1; gate = z & 1;
        src = (gate ? Wres : Wskip) + (size_t)l * 128 * 128;
        dhi = g_WpHi; dlo = g_WpLo;
        obase = (size_t)l * 256 * 128;
    }
    #pragma unroll
    for (int r = 0; r < 4; r++)
        t[ty + r*8][tx] = src[(ci0 + ty + r*8) * 128 + co0 + tx];
    __syncthreads();
    #pragma unroll
    for (int r = 0; r < 4; r++) {
        float v = t[tx][ty + r*8];
        int n = gate * 128 + co0 + ty + r*8;
        size_t o = obase + (size_t)n * 128 + ci0 + tx;
        __nv_bfloat16 h = __float2bfloat16(v);
        dhi[o] = h;
        dlo[o] = __float2bfloat16(v - __bfloat162float(h));
    }
}

__global__ void k_cvtWhead(const float* __restrict__ W1, const float* __restrict__ W2,
                           __nv_bfloat16* __restrict__ w1h, __nv_bfloat16* __restrict__ w1l,
                           __nv_bfloat16* __restrict__ w2h, __nv_bfloat16* __restrict__ w2l) {
    __shared__ float t[32][33];
    int id = blockIdx.x;
    const float* src; __nv_bfloat16 *dhi, *dlo;
    int K, N, n0, k0, tap;
    if (id < 768) {
        tap = id / 256; int rem = id % 256;
        n0 = (rem & 63) * 32; k0 = (rem >> 6) * 32;
        src = W1; dhi = w1h; dlo = w1l; K = 128; N = 2048;
    } else {
        id -= 768;
        tap = id / 512; int rem = id % 512;
        n0 = (rem & 7) * 32; k0 = (rem >> 3) * 32;
        src = W2; dhi = w2h; dlo = w2l; K = 2048; N = 256;
    }
    int tx = threadIdx.x, ty = threadIdx.y;
    #pragma unroll
    for (int r = 0; r < 4; r++)
        t[ty + r*8][tx] = src[((size_t)tap*K + k0 + ty + r*8) * N + n0 + tx];
    __syncthreads();
    #pragma unroll
    for (int r = 0; r < 4; r++) {
        float v = t[tx][ty + r*8];
        __nv_bfloat16 h = __float2bfloat16(v);
        __nv_bfloat16 l = __float2bfloat16(v - __bfloat162float(h));
        size_t o = ((size_t)tap*N + n0 + ty + r*8) * K + k0 + tx;
        dhi[o] = h; dlo[o] = l;
    }
}

// ---------------------------------------------------------------------------
__global__ __launch_bounds__(256) void k_condpre(
    const float* __restrict__ cond,
    const float* __restrict__ Dt, const float* __restrict__ Ds,
    const float* __restrict__ Bt, const float* __restrict__ Bs,
    const float* __restrict__ bt, const float* __restrict__ bs, int l)
{
    const int tid = threadIdx.x;
    const int co = (tid & 31) << 2;
    const int gate = (tid >> 5) & 1;
    const int tq = tid >> 6;
    const int t0 = blockIdx.x * 8 + tq;

    __shared__ float sc[NB][NCOND];
    if (tid < NB * NCOND) sc[tid >> 4][tid & 15] = cond[tid];
    __syncthreads();

    const float* D  = gate ? Ds : Dt;
    const float* Bm = gate ? Bs : Bt;
    float4 bias = *(const float4*)((gate ? bs : bt) + l * 128 + co);

    float4 acc[2][NB];
    #pragma unroll
    for (int tt = 0; tt < 2; tt++)
        #pragma unroll
        for (int b = 0; b < NB; b++) acc[tt][b] = make_float4(0.f, 0.f, 0.f, 0.f);

    #pragma unroll 4
    for (int c = 0; c < NCOND; c++) {
        size_t base = (((size_t)l * NCOND + c) * TT + t0) * 128 + co;
        float4 d0 = *(const float4*)(D + base);
        float4 d1 = *(const float4*)(D + base + 4 * 128);
        #pragma unroll
        for (int b = 0; b < NB; b++) {
            float s = sc[b][c];
            acc[0][b].x = fmaf(s, d0.x, acc[0][b].x);
            acc[0][b].y = fmaf(s, d0.y, acc[0][b].y);
            acc[0][b].z = fmaf(s, d0.z, acc[0][b].z);
            acc[0][b].w = fmaf(s, d0.w, acc[0][b].w);
            acc[1][b].x = fmaf(s, d1.x, acc[1][b].x);
            acc[1][b].y = fmaf(s, d1.y, acc[1][b].y);
            acc[1][b].z = fmaf(s, d1.z, acc[1][b].z);
            acc[1][b].w = fmaf(s, d1.w, acc[1][b].w);
        }
    }
    #pragma unroll
    for (int tt = 0; tt < 2; tt++) {
        int t = t0 + tt * 4;
        float4 bm = *(const float4*)(Bm + ((size_t)l * TT + t) * 128 + co);
        bm.x += bias.x; bm.y += bias.y; bm.z += bias.z; bm.w += bias.w;
        #pragma unroll
        for (int b = 0; b < NB; b++) {
            float4 v = acc[tt][b];
            v.x += bm.x; v.y += bm.y; v.z += bm.z; v.w += bm.w;
            *(float4*)(g_tcond + (((size_t)l * NB + b) * TT + t) * 256
                       + gate * 128 + co) = v;
        }
    }
}

// ---------------------------------------------------------------------------
// Fused residual layer: 1024 threads (32 warps) for latency hiding.
// Epilogues use x16/x32 LDTM to stay under the 64 reg/thread budget.
// ---------------------------------------------------------------------------
#define LAYER_SMEM 200704

__global__ __launch_bounds__(1024, 1) void k_layer(
    int l, int d, const float* __restrict__ bskip, const float* __restrict__ bres)
{
#if HAS_TCGEN05
    extern __shared__ char dsm[];
    const int tid = threadIdx.x;
    const int wid = tid >> 5;
    const int lane = tid & 31;

    uint32_t raw = smem_to_u32(dsm);
    uint32_t abase = (raw + 1023) & ~1023u;
    char* hdr = dsm + (abase - raw);
    char* G   = hdr + 2048;
    const uint32_t hdr_a = abase;
    const uint32_t G_a   = abase + 2048;

    const int b  = blockIdx.x >> 4;
    const int t0 = (blockIdx.x & 15) << 7;

    if (tid == 0) {
        MBARRIER_INIT(hdr_a + 8, 1);
        MBARRIER_INIT(hdr_a + 16, 1);
    }
    if (wid == 0) TCGEN05_ALLOC(hdr_a, 512);
    __syncthreads();

    uint32_t tmem;
    asm volatile("ld.shared.b32 %0, [%1];" : "=r"(tmem) : "r"(hdr_a));

    int phase[2] = {0, 0};

    // ---- gate phase: 6 chunks ----
    for (int ch = 0; ch < 6; ch++) {
        const int buf = ch & 1;
        char* Gb = G + buf * 98304;
        const uint32_t Gb_a = G_a + buf * 98304;
        const int tap = ch >> 1;
        const int ci0 = (ch & 1) << 6;

        // A: thread = (row r8 = tid>>3, uint4-col oc = tid&7): 1 hi + 1 lo
        uint4 va[2];
        const int r8 = tid >> 3, oc = tid & 7;
        {
            int trow = t0 + r8 + (tap - 1) * d;
            bool ok = (unsigned)trow < (unsigned)TT;
            size_t goff = ((size_t)(b * TT + (ok ? trow : 0))) * NC + ci0 + oc * 8;
            if (ok) {
                va[0] = *(const uint4*)(g_hHi + goff);
                va[1] = *(const uint4*)(g_hLo + goff);
            } else {
                va[0] = make_uint4(0,0,0,0);
                va[1] = make_uint4(0,0,0,0);
            }
        }
        // B: thread = (row rb = tid>>2, pair cb = tid&3): 2 hi + 2 lo
        uint4 wb[4];
        const int rb = tid >> 2, cb = tid & 3;
        {
            size_t woff = (((size_t)(l * 3 + tap)) * 256 + rb) * 128 + ci0 + cb * 16;
            wb[0] = *(const uint4*)(g_WgHi + woff);
            wb[1] = *(const uint4*)(g_WgHi + woff + 8);
            wb[2] = *(const uint4*)(g_WgLo + woff);
            wb[3] = *(const uint4*)(g_WgLo + woff + 8);
        }

        if (ch >= 2) {
            MBARRIER_WAIT_PARITY(hdr_a + 8 + 8 * buf, phase[buf]);
            phase[buf] ^= 1;
        }

        {
            uint32_t so = r8 * 128 + (((uint32_t)(oc ^ (r8 & 7))) << 4);
            *(uint4*)(Gb + so)         = va[0];
            *(uint4*)(Gb + 16384 + so) = va[1];
        }
        #pragma unroll
        for (int q = 0; q < 2; q++) {
            int c = cb * 2 + q;
            uint32_t so = rb * 128 + (((uint32_t)(c ^ (rb & 7))) << 4);
            *(uint4*)(Gb + 32768 + so) = wb[q];
            *(uint4*)(Gb + 65536 + so) = wb[2 + q];
        }
        FENCE_PROXY_ASYNC_SHARED_CTA();
        __syncthreads();

        if (wid == 0 && elect_one_pred()) {
            u64 dAh = MAKE_SMEM_DESC(Gb_a);
            u64 dAl = MAKE_SMEM_DESC(Gb_a + 16384);
            u64 dBh = MAKE_SMEM_DESC(Gb_a + 32768);
            u64 dBl = MAKE_SMEM_DESC(Gb_a + 65536);
            uint32_t en = (ch != 0);
            #pragma unroll
            for (int ks = 0; ks < 4; ks++) {
                mma_bf16_ss(tmem, dAh + 2*ks, dBh + 2*ks, IDESC_N256, en); en = 1;
                mma_bf16_ss(tmem, dAh + 2*ks, dBl + 2*ks, IDESC_N256, 1);
                mma_bf16_ss(tmem, dAl + 2*ks, dBh + 2*ks, IDESC_N256, 1);
            }
            TCGEN05_COMMIT(hdr_a + 8 + 8 * buf);
        }
    }

    MBARRIER_WAIT_PARITY(hdr_a + 8,  phase[0]);
    MBARRIER_WAIT_PARITY(hdr_a + 16, phase[1]);
    const int postPh = phase[0] ^ 1;
    TCGEN05_FENCE_AFTER();
    __syncthreads();

    // ---- stage tcond coalesced into smem [t 128][260 f] ----
    float* tcS = (float*)(G + 65536);
    {
        const float* tcg = g_tcond + (((size_t)l * NB + b) * TT + t0) * 256;
        #pragma unroll
        for (int k = 0; k < 8; k++) {
            int i4 = tid + k * 1024;
            int row = i4 >> 6, c4 = (i4 & 63) << 2;
            float4 v = *(const float4*)(tcg + (size_t)row * 256 + c4);
            *(float4*)(tcS + row * 260 + c4) = v;
        }
    }
    __syncthreads();

    // ---- epilogue 1 (32 warps: rows (wid&3)*32, col group (wid>>2)*16) ----
    {
        const int row = (wid & 3) * 32 + lane;
        const int c0 = (wid >> 2) * 16;
        const float* trow_ = tcS + row * 260;
        uint32_t rt[16], rs[16];
        TCGEN05_LD_32X32B_X16(rt, tmem + c0);
        TCGEN05_LD_32X32B_X16(rs, tmem + 128 + c0);
        TCGEN05_WAIT_LD();
        #pragma unroll
        for (int j = 0; j < 16; j += 4) {
            int c = c0 + j;
            float4 ta = *(const float4*)(trow_ + c);
            float4 tx = *(const float4*)(trow_ + 128 + c);
            float av[4] = {__uint_as_float(rt[j])   + ta.x,
                           __uint_as_float(rt[j+1]) + ta.y,
                           __uint_as_float(rt[j+2]) + ta.z,
                           __uint_as_float(rt[j+3]) + ta.w};
            float xv[4] = {__uint_as_float(rs[j])   + tx.x,
                           __uint_as_float(rs[j+1]) + tx.y,
                           __uint_as_float(rs[j+2]) + tx.z,
                           __uint_as_float(rs[j+3]) + tx.w};
            __nv_bfloat16 hv[4], lv[4];
            #pragma unroll
            for (int q = 0; q < 4; q++) {
                float gv = gate_act(av[q], xv[q]);
                hv[q] = __float2bfloat16(gv);
                lv[q] = __float2bfloat16(gv - __bfloat162float(hv[q]));
            }
            uint32_t off = row * 128 + (c & 63) * 2;
            off ^= (off >> 3) & 0x70;
            char* atp = G + ((c >> 6) * 32768);
            *(uint2*)(atp + off)         = *(const uint2*)hv;
            *(uint2*)(atp + 16384 + off) = *(const uint2*)lv;
        }
    }
    __syncthreads();

    // ---- post weights into G+65536..196608 ----
    {
        const int r = tid >> 2, cb2 = tid & 3;
        size_t woff = ((size_t)l * 256 + r) * 128;
        #pragma unroll
        for (int cc = 0; cc < 2; cc++) {
            char* dst = G + 65536 + cc * 65536;
            #pragma unroll
            for (int q = 0; q < 2; q++) {
                int c = cb2 * 2 + q;
                uint32_t so = r * 128 + (((uint32_t)(c ^ (r & 7))) << 4);
                *(uint4*)(dst + so)         = *(const uint4*)(g_WpHi + woff + cc*64 + c*8);
                *(uint4*)(dst + 32768 + so) = *(const uint4*)(g_WpLo + woff + cc*64 + c*8);
            }
        }
    }
    FENCE_PROXY_ASYNC_SHARED_CTA();
    __syncthreads();

    // ---- post MMA -> tmem cols 256..511 ----
    if (wid == 0 && elect_one_pred()) {
        uint32_t en = 0;
        #pragma unroll
        for (int cc = 0; cc < 2; cc++) {
            u64 dAh = MAKE_SMEM_DESC(G_a + cc * 32768);
            u64 dAl = MAKE_SMEM_DESC(G_a + cc * 32768 + 16384);
            u64 dBh = MAKE_SMEM_DESC(G_a + 65536 + cc * 65536);
            u64 dBl = MAKE_SMEM_DESC(G_a + 65536 + cc * 65536 + 32768);
            #pragma unroll
            for (int ks = 0; ks < 4; ks++) {
                mma_bf16_ss(tmem + 256, dAh + 2*ks, dBh + 2*ks, IDESC_N256, en); en = 1;
                mma_bf16_ss(tmem + 256, dAh + 2*ks, dBl + 2*ks, IDESC_N256, 1);
                mma_bf16_ss(tmem + 256, dAl + 2*ks, dBh + 2*ks, IDESC_N256, 1);
            }
        }
        TCGEN05_COMMIT(hdr_a + 8);
    }
    MBARRIER_WAIT_PARITY(hdr_a + 8, postPh);
    TCGEN05_FENCE_AFTER();
    __syncthreads();

    // ---- epilogue 2a (32 warps): stage D2 into smem [row][260 f] ----
    float* st = (float*)G;
    {
        const int row = (wid & 3) * 32 + lane;
        const int c0 = (wid >> 2) * 32;
        uint32_t ra[32];
        TCGEN05_LD_32X32B_X32(ra, tmem + 256 + c0);
        TCGEN05_WAIT_LD();
        #pragma unroll
        for (int j = 0; j < 32; j += 4) {
            float4 v1 = make_float4(__uint_as_float(ra[j]),   __uint_as_float(ra[j+1]),
                                    __uint_as_float(ra[j+2]), __uint_as_float(ra[j+3]));
            *(float4*)(st + row * 260 + c0 + j) = v1;
        }
    }
    __syncthreads();

    // ---- epilogue 2b: coalesced RMW of skip/h; last layer -> skip split ----
    {
        const size_t gbase = ((size_t)(b * TT + t0)) * NC;
        const bool lastL = (l == NL - 1);
        #pragma unroll
        for (int k = 0; k < 4; k++) {
            int e = tid + k * 1024;
            int row = e >> 5, c4 = (e & 31) << 2;
            float4 dsk = *(const float4*)(st + row * 260 + c4);
            float4 bk4 = *(const float4*)(bskip + l * 128 + c4);
            size_t go = gbase + (size_t)row * NC + c4;
            float4 sk = *(const float4*)(g_skip + go);
            sk.x += dsk.x + bk4.x; sk.y += dsk.y + bk4.y;
            sk.z += dsk.z + bk4.z; sk.w += dsk.w + bk4.w;
            if (!lastL) {
                float4 dre = *(const float4*)(st + row * 260 + 128 + c4);
                float4 br4 = *(const float4*)(bres  + l * 128 + c4);
                float4 hh = *(const float4*)(g_h + go);
                hh.x += dre.x + br4.x; hh.y += dre.y + br4.y;
                hh.z += dre.z + br4.z; hh.w += dre.w + br4.w;
                *(float4*)(g_skip + go) = sk;
                *(float4*)(g_h + go) = hh;
                float hq[4] = {hh.x, hh.y, hh.z, hh.w};
                __nv_bfloat16 hv[4], lv[4];
                #pragma unroll
                for (int q = 0; q < 4; q++) {
                    hv[q] = __float2bfloat16(hq[q]);
                    lv[q] = __float2bfloat16(hq[q] - __bfloat162float(hv[q]));
                }
                *(uint2*)(g_hHi + go) = *(const uint2*)hv;
                *(uint2*)(g_hLo + go) = *(const uint2*)lv;
            } else {
                float sq[4] = {sk.x, sk.y, sk.z, sk.w};
                __nv_bfloat16 hv[4], lv[4];
                #pragma unroll
                for (int q = 0; q < 4; q++) {
                    hv[q] = __float2bfloat16(sq[q]);
                    lv[q] = __float2bfloat16(sq[q] - __bfloat162float(hv[q]));
                }
                *(uint2*)(g_skipHi + go) = *(const uint2*)hv;
                *(uint2*)(g_skipLo + go) = *(const uint2*)lv;
            }
        }
    }
    __syncthreads();
    if (wid == 0) {
        TCGEN05_RELINQUISH_ALLOC_PERMIT();
        TCGEN05_DEALLOC(tmem, 512);
    }
#endif // HAS_TCGEN05
}

// ---------------------------------------------------------------------------
// Head GEMM-conv3, TWO N-tiles per CTA (round-13 validated, unchanged).
// ---------------------------------------------------------------------------
#define GEMM_SMEM 200704

template<bool WB16>
__global__ __launch_bounds__(256, 1) void k_gemm(
    const __nv_bfloat16* __restrict__ aHi, const __nv_bfloat16* __restrict__ aLo,
    const __nv_bfloat16* __restrict__ wHi, const __nv_bfloat16* __restrict__ wLo,
    const float* __restrict__ bias,
    __nv_bfloat16* __restrict__ oHi, __nv_bfloat16* __restrict__ oLo,
    float* __restrict__ oF, int Cin, int CO)
{
#if HAS_TCGEN05
    extern __shared__ char dsm[];
    const int tid = threadIdx.x;
    const int wid = tid >> 5;
    const int lane = tid & 31;

    uint32_t raw = smem_to_u32(dsm);
    uint32_t abase = (raw + 1023) & ~1023u;
    char* hdr   = dsm + (abase - raw);
    char* G     = hdr + 2048;
    const uint32_t hdr_a = abase;
    const uint32_t G_a   = abase + 2048;
    float* sbias = (float*)(hdr + 1024);

    const int b  = blockIdx.x >> 4;
    const int t0 = (blockIdx.x & 15) * 128;
    const int n0 = blockIdx.y * 256;

    if (tid == 0) {
        MBARRIER_INIT(hdr_a + 8, 1);
        MBARRIER_INIT(hdr_a + 16, 1);
    }
    if (wid == 0) TCGEN05_ALLOC(hdr_a, 256);
    sbias[tid] = bias[n0 + tid];
    __syncthreads();

    uint32_t tmem;
    asm volatile("ld.shared.b32 %0, [%1];" : "=r"(tmem) : "r"(hdr_a));

    const int nci = Cin >> 6;
    const int nchunks = 3 * nci;
    const size_t aBatch = (size_t)b * TT * Cin;

    int phase[2] = {0, 0};

    for (int ch = 0; ch < nchunks; ch++) {
        const int buf = ch & 1;
        char* tb = G + buf * 98304;
        const uint32_t tb_a = G_a + buf * 98304;

        const int tap = ch / nci;
        const int ci0 = (ch - tap * nci) << 6;
        const size_t bBase0 = ((size_t)tap * CO + n0) * Cin + ci0;
        const int c = tid & 7;

        uint4 va[8], vb0[8];
        #pragma unroll
        for (int p = 0; p < 4; p++) {
            int r = p * 32 + (tid >> 3);
            int trow = t0 + r + tap - 1;
            if ((unsigned)trow < (unsigned)TT) {
                size_t off = aBatch + (size_t)trow * Cin + ci0 + c * 8;
                va[p]     = *(const uint4*)(aHi + off);
                va[4 + p] = *(const uint4*)(aLo + off);
            } else {
                va[p] = make_uint4(0,0,0,0);
                va[4 + p] = make_uint4(0,0,0,0);
            }
            size_t bo = bBase0 + (size_t)r * Cin + c * 8;
            vb0[p]     = *(const uint4*)(wHi + bo);
            vb0[4 + p] = *(const uint4*)(wLo + bo);
        }

        if (ch >= 2) {
            MBARRIER_WAIT_PARITY(hdr_a + 8 + 8 * buf, phase[buf]);
            phase[buf] ^= 1;
        }

        #pragma unroll
        for (int p = 0; p < 4; p++) {
            int r = p * 32 + (tid >> 3);
            uint32_t so = r * 128 + (((uint32_t)(c ^ (r & 7))) << 4);
            *(uint4*)(tb + so)         = va[p];
            *(uint4*)(tb + 16384 + so) = va[4 + p];
            *(uint4*)(tb + 32768 + so) = vb0[p];
            *(uint4*)(tb + 49152 + so) = vb0[4 + p];
        }
        {
            const size_t bBase1 = bBase0 + (size_t)128 * Cin;
            #pragma unroll
            for (int p = 0; p < 4; p++) {
                int r = p * 32 + (tid >> 3);
                size_t bo = bBase1 + (size_t)r * Cin + c * 8;
                uint4 h4 = *(const uint4*)(wHi + bo);
                uint4 l4 = *(const uint4*)(wLo + bo);
                uint32_t so = r * 128 + (((uint32_t)(c ^ (r & 7))) << 4);
                *(uint4*)(tb + 65536 + so) = h4;
                *(uint4*)(tb + 81920 + so) = l4;
            }
        }
        FENCE_PROXY_ASYNC_SHARED_CTA();
        __syncthreads();

        if (wid == 0 && elect_one_pred()) {
            u64 dAh  = MAKE_SMEM_DESC(tb_a);
            u64 dAl  = MAKE_SMEM_DESC(tb_a + 16384);
            u64 dB0h = MAKE_SMEM_DESC(tb_a + 32768);
            u64 dB0l = MAKE_SMEM_DESC(tb_a + 49152);
            u64 dB1h = MAKE_SMEM_DESC(tb_a + 65536);
            u64 dB1l = MAKE_SMEM_DESC(tb_a + 81920);
            uint32_t en = (ch != 0);
            #pragma unroll
            for (int ks = 0; ks < 4; ks++) {
                mma_bf16_ss(tmem,       dAh + 2*ks, dB0h + 2*ks, GEMM_IDESC, en);
                mma_bf16_ss(tmem + 128, dAh + 2*ks, dB1h + 2*ks, GEMM_IDESC, en);
                en = 1;
                mma_bf16_ss(tmem,       dAh + 2*ks, dB0l + 2*ks, GEMM_IDESC, 1);
                mma_bf16_ss(tmem,       dAl + 2*ks, dB0h + 2*ks, GEMM_IDESC, 1);
                mma_bf16_ss(tmem + 128, dAh + 2*ks, dB1l + 2*ks, GEMM_IDESC, 1);
                mma_bf16_ss(tmem + 128, dAl + 2*ks, dB1h + 2*ks, GEMM_IDESC, 1);
            }
            TCGEN05_COMMIT(hdr_a + 8 + 8 * buf);
        }
    }

    MBARRIER_WAIT_PARITY(hdr_a + 8,  phase[0]);
    MBARRIER_WAIT_PARITY(hdr_a + 16, phase[1]);
    TCGEN05_FENCE_AFTER();
    __syncthreads();

    #pragma unroll 1
    for (int nt = 0; nt < 2; nt++) {
        const uint32_t dbase = tmem + nt * 128;
        const int nb = n0 + nt * 128;
        if (WB16) {
            char* hiS = G;
            char* loS = G + 34816;
            {
                const int m = (wid & 3) * 32 + lane;
                const int cg = (wid >> 2) * 64;
                #pragma unroll 1
                for (int half2 = 0; half2 < 2; half2++) {
                    int c0 = cg + half2 * 32;
                    uint32_t r32[32];
                    TCGEN05_LD_32X32B_X32(r32, dbase + c0);
                    TCGEN05_WAIT_LD();
                    #pragma unroll
                    for (int j = 0; j < 32; j += 2) {
                        __nv_bfloat16 hv[2], lv[2];
                        #pragma unroll
                        for (int q = 0; q < 2; q++) {
                            float v = __uint_as_float(r32[j+q]) + sbias[nt*128 + c0 + j + q];
                            v = fmaxf(v, 0.f);
                            hv[q] = __float2bfloat16(v);
                            lv[q] = __float2bfloat16(v - __bfloat162float(hv[q]));
                        }
                        uint32_t so = m * 272 + (c0 + j) * 2;
                        *(uint32_t*)(hiS + so) = *(const uint32_t*)hv;
                        *(uint32_t*)(loS + so) = *(const uint32_t*)lv;
                    }
                }
            }
            __syncthreads();
            #pragma unroll
            for (int k = 0; k < 8; k++) {
                int e = tid + k * 256;
                int row = e >> 4, cu = e & 15;
                uint4 h4 = *(const uint4*)(hiS + row * 272 + cu * 16);
                uint4 l4 = *(const uint4*)(loS + row * 272 + cu * 16);
                size_t o = (size_t)(b * TT + t0 + row) * CO + nb + cu * 8;
                *(uint4*)(oHi + o) = h4;
                *(uint4*)(oLo + o) = l4;
            }
            __syncthreads();
        } else {
            float* fS = (float*)G;
            {
                const int m = (wid & 3) * 32 + lane;
                const int cg = (wid >> 2) * 64;
                #pragma unroll 1
                for (int half2 = 0; half2 < 2; half2++) {
                    int c0 = cg + half2 * 32;
                    uint32_t r32[32];
                    TCGEN05_LD_32X32B_X32(r32, dbase + c0);
                    TCGEN05_WAIT_LD();
                    #pragma unroll
                    for (int j = 0; j < 32; j += 4) {
                        float4 v;
                        v.x = fmaxf(__uint_as_float(r32[j])   + sbias[nt*128 + c0+j],   0.f);
                        v.y = fmaxf(__uint_as_float(r32[j+1]) + sbias[nt*128 + c0+j+1], 0.f);
                        v.z = fmaxf(__uint_as_float(r32[j+2]) + sbias[nt*128 + c0+j+2], 0.f);
                        v.w = fmaxf(__uint_as_float(r32[j+3]) + sbias[nt*128 + c0+j+3], 0.f);
                        *(float4*)(fS + m * 132 + c0 + j) = v;
                    }
                }
            }
            __syncthreads();
            #pragma unroll
            for (int k = 0; k < 16; k++) {
                int e = tid + k * 256;
                int row = e >> 5, c4 = (e & 31) << 2;
                float4 v = *(const float4*)(fS + row * 132 + c4);
                *(float4*)(oF + (size_t)(b * TT + t0 + row) * CO + nb + c4) = v;
            }
            __syncthreads();
        }
    }

    if (wid == 0) {
        TCGEN05_RELINQUISH_ALLOC_PERMIT();
        TCGEN05_DEALLOC(tmem, 256);
    }
#endif // HAS_TCGEN05
}

// ---------------------------------------------------------------------------
__global__ __launch_bounds__(128) void k_head3(const float* __restrict__ W3,
                                               const float* __restrict__ b3,
                                               float* __restrict__ out)
{
    int row  = blockIdx.x * 4 + (threadIdx.x >> 5);
    int lane = threadIdx.x & 31;
    const float* p = g_out2 + (size_t)row * 256;
    float s = 0.f;
    #pragma unroll
    for (int i = 0; i < 8; i++) s = fmaf(p[lane + 32 * i], W3[lane + 32 * i], s);
    #pragma unroll
    for (int o = 16; o; o >>= 1) s += __shfl_xor_sync(0xffffffffu, s, o);
    if (lane == 0) out[row] = tanhf(s + b3[0]);
}

// ---------------------------------------------------------------------------
static cudaStream_t s_side = nullptr;
static cudaEvent_t  s_evFork = nullptr;
static cudaEvent_t  s_evW = nullptr;
static cudaEvent_t  s_evL[NL];

extern "C" void kernel_launch(void* const* d_in, const int* in_sizes, int n_in,
                              void* d_out, int out_size) {
    const float* x     = (const float*)d_in[0];
    const float* cond  = (const float*)d_in[1];
    const float* Wc    = (const float*)d_in[2];
    const float* bc    = (const float*)d_in[3];
    const float* Wt    = (const float*)d_in[4];
    const float* bt    = (const float*)d_in[5];
    const float* Ws    = (const float*)d_in[6];
    const float* bs    = (const float*)d_in[7];
    const float* Dt    = (const float*)d_in[8];
    const float* Bt    = (const float*)d_in[9];
    const float* Ds    = (const float*)d_in[10];
    const float* Bs    = (const float*)d_in[11];
    const float* Wskip = (const float*)d_in[12];
    const float* bskip = (const float*)d_in[13];
    const float* Wres  = (const float*)d_in[14];
    const float* bres  = (const float*)d_in[15];
    const float* W1    = (const float*)d_in[16];
    const float* b1    = (const float*)d_in[17];
    const float* W2    = (const float*)d_in[18];
    const float* b2    = (const float*)d_in[19];
    const float* W3    = (const float*)d_in[20];
    const float* b3    = (const float*)d_in[21];
    float* out = (float*)d_out;

    if (!s_side) {
        cudaStreamCreateWithFlags(&s_side, cudaStreamNonBlocking);
        cudaEventCreateWithFlags(&s_evFork, cudaEventDisableTiming);
        cudaEventCreateWithFlags(&s_evW, cudaEventDisableTiming);
        for (int l = 0; l < NL; l++)
            cudaEventCreateWithFlags(&s_evL[l], cudaEventDisableTiming);
    }

    cudaFuncSetAttribute(k_layer, cudaFuncAttributeMaxDynamicSharedMemorySize, LAYER_SMEM);
    cudaFuncSetAttribute(k_gemm<true>,  cudaFuncAttributeMaxDynamicSharedMemorySize, GEMM_SMEM);
    cudaFuncSetAttribute(k_gemm<false>, cudaFuncAttributeMaxDynamicSharedMemorySize, GEMM_SMEM);

    __nv_bfloat16 *skipHi, *skipLo, *w1h, *w1l, *w2h, *w2l, *o1h, *o1l;
    float* out2p;
    cudaGetSymbolAddress((void**)&skipHi, g_skipHi);
    cudaGetSymbolAddress((void**)&skipLo, g_skipLo);
    cudaGetSymbolAddress((void**)&w1h, g_W1tHi);
    cudaGetSymbolAddress((void**)&w1l, g_W1tLo);
    cudaGetSymbolAddress((void**)&w2h, g_W2tHi);
    cudaGetSymbolAddress((void**)&w2l, g_W2tLo);
    cudaGetSymbolAddress((void**)&o1h, g_out1Hi);
    cudaGetSymbolAddress((void**)&o1l, g_out1Lo);
    cudaGetSymbolAddress((void**)&out2p, g_out2);

    const int dil[NL] = {1, 2, 4, 8, 16, 32, 64, 128, 256, 512};

    // main stream; k_layer(0) is the 4th launch (ncu profiles the 4th)
    k_condpre<<<TT/8, 256>>>(cond, Dt, Ds, Bt, Bs, bt, bs, 0);     // 1
    k_cvtStack<<<1280, 256>>>(Wt, Ws, Wskip, Wres);                // 2
    k_init<<<NB * TT * NC / 256, 256>>>(x, Wc, bc);                // 3
    k_layer<<<NB * (TT/128), 1024, LAYER_SMEM>>>(0, dil[0], bskip, bres); // 4

    // side stream: head-weight conversion + remaining condpre slices
    cudaEventRecord(s_evFork, 0);
    cudaStreamWaitEvent(s_side, s_evFork, 0);
    k_cvtWhead<<<2304, dim3(32, 8), 0, s_side>>>(W1, W2, w1h, w1l, w2h, w2l);
    cudaEventRecord(s_evW, s_side);
    for (int l = 1; l < NL; l++) {
        k_condpre<<<TT/8, 256, 0, s_side>>>(cond, Dt, Ds, Bt, Bs, bt, bs, l);
        cudaEventRecord(s_evL[l], s_side);
    }
    for (int l = 1; l < NL; l++) {
        cudaStreamWaitEvent(0, s_evL[l], 0);
        k_layer<<<NB * (TT/128), 1024, LAYER_SMEM>>>(l, dil[l], bskip, bres);
    }

    // heads (gated on head-weight conversion)
    cudaStreamWaitEvent(0, s_evW, 0);
    k_gemm<true><<<dim3(128, 8), 256, GEMM_SMEM>>>(
        skipHi, skipLo, w1h, w1l, b1, o1h, o1l, nullptr, 128, 2048);
    k_gemm<false><<<dim3(128, 1), 256, GEMM_SMEM>>>(
        o1h, o1l, w2h, w2l, b2, nullptr, nullptr, out2p, 2048, 256);

    k_head3<<<NB * TT / 4, 128>>>(W3, b3, out);
}

// round 17
// speedup vs baseline: 1.2878x; 1.0090x over previous
#include <cuda_runtime.h>
#include <cuda_bf16.h>
#include <math.h>
#include <stdint.h>

#define TT    2048
#define NB    8
#define NC    128
#define NCOND 16
#define NL    10

#if defined(__CUDA_ARCH_FEAT_SM103_ALL) || defined(__CUDA_ARCH_FEAT_SM100_ALL) || defined(__CUDA_ARCH_FEAT_SM101_ALL)
#define HAS_TCGEN05 1
#else
#define HAS_TCGEN05 0
#endif

typedef unsigned long long u64;

// ---------------------------------------------------------------------------
// Device scratch
// ---------------------------------------------------------------------------
__device__ float g_h   [NB*TT*NC];
__device__ float g_skip[NB*TT*NC];
__device__ float g_out2[NB*TT*256];
__device__ float g_tcond[(size_t)NL*NB*TT*256];

__device__ __nv_bfloat16 g_hHi  [NB*TT*NC];
__device__ __nv_bfloat16 g_hLo  [NB*TT*NC];
__device__ __nv_bfloat16 g_WgHi [NL*3*256*128];
__device__ __nv_bfloat16 g_WgLo [NL*3*256*128];
__device__ __nv_bfloat16 g_WpHi [NL*256*128];
__device__ __nv_bfloat16 g_WpLo [NL*256*128];

__device__ __nv_bfloat16 g_skipHi[NB*TT*NC];
__device__ __nv_bfloat16 g_skipLo[NB*TT*NC];
__device__ __nv_bfloat16 g_W1tHi [3*2048*128];
__device__ __nv_bfloat16 g_W1tLo [3*2048*128];
__device__ __nv_bfloat16 g_W2tHi [3*256*2048];
__device__ __nv_bfloat16 g_W2tLo [3*256*2048];
__device__ __nv_bfloat16 g_out1Hi[(size_t)NB*TT*2048];
__device__ __nv_bfloat16 g_out1Lo[(size_t)NB*TT*2048];

// ---------------------------------------------------------------------------
// helpers
// ---------------------------------------------------------------------------
__device__ __forceinline__ uint32_t smem_to_u32(const void* p) {
    uint32_t a;
    asm("{ .reg .u64 t; cvta.to.shared.u64 t, %1; cvt.u32.u64 %0, t; }"
        : "=r"(a) : "l"(p));
    return a;
}
__device__ __forceinline__ float rcp_fast(float x) {
    float r; asm("rcp.approx.f32 %0, %1;" : "=f"(r) : "f"(x)); return r;
}
__device__ __forceinline__ float gate_act(float a, float x) {
    a = fminf(fmaxf(a, -15.f), 15.f);
    x = fminf(fmaxf(x, -15.f), 15.f);
    float E = __expf(2.f * a);
    float F = __expf(x);
    float r = rcp_fast((E + 1.f) * (F + 1.f));
    return (E - 1.f) * F * r;
}

#if HAS_TCGEN05
__device__ __forceinline__ uint32_t elect_one_pred() {
    uint32_t pred;
    asm volatile(
        "{\n\t.reg .pred p;\n\telect.sync _|p, 0xFFFFFFFF;\n\t"
        "selp.b32 %0, 1, 0, p;\n\t}" : "=r"(pred));
    return pred;
}

#define TCGEN05_ALLOC(smem_result_addr, nCols) \
    asm volatile("tcgen05.alloc.cta_group::1.sync.aligned.shared::cta.b32 [%0], %1;" \
        :: "r"((uint32_t)(smem_result_addr)), "r"((uint32_t)(nCols)) : "memory")
#define TCGEN05_DEALLOC(tmem_addr, nCols) \
    asm volatile("tcgen05.dealloc.cta_group::1.sync.aligned.b32 %0, %1;" \
        :: "r"(tmem_addr), "r"((uint32_t)(nCols)))
#define TCGEN05_RELINQUISH_ALLOC_PERMIT() \
    asm volatile("tcgen05.relinquish_alloc_permit.cta_group::1.sync.aligned;")
#define TCGEN05_COMMIT(mbar_smem_addr) \
    asm volatile("tcgen05.commit.cta_group::1.mbarrier::arrive::one.shared::cluster.b64 [%0];" \
        :: "r"((uint32_t)(mbar_smem_addr)) : "memory")
#define TCGEN05_FENCE_AFTER() \
    asm volatile("tcgen05.fence::after_thread_sync;" ::: "memory")
#define TCGEN05_WAIT_LD() \
    asm volatile("tcgen05.wait::ld.sync.aligned;" ::: "memory")
#define FENCE_PROXY_ASYNC_SHARED_CTA() \
    asm volatile("fence.proxy.async.shared::cta;" ::: "memory")
#define MBARRIER_INIT(mbar_smem_addr, count) \
    asm volatile("mbarrier.init.shared.b64 [%0], %1;" \
        :: "r"((uint32_t)(mbar_smem_addr)), "r"((uint32_t)(count)) : "memory")

#define MBARRIER_WAIT_PARITY(mbar_smem_addr, phase_parity) do { \
    uint32_t _mbar = (uint32_t)(mbar_smem_addr); \
    uint32_t _parity = (uint32_t)(phase_parity); \
    uint32_t _done; \
    asm volatile( \
        "{\n\t.reg .pred p;\n\t" \
        "mbarrier.try_wait.parity.acquire.cta.shared::cta.b64 p, [%1], %2;\n\t" \
        "selp.b32 %0, 1, 0, p;\n\t}" \
        : "=r"(_done) : "r"(_mbar), "r"(_parity) : "memory"); \
    if (!_done) { \
        asm volatile( \
            "{\n\t.reg .pred P1;\n\t" \
            "WAIT_LOOP_%=:\n\t" \
            "mbarrier.try_wait.parity.acquire.cta.shared::cta.b64 P1, [%0], %1, 0x989680;\n\t" \
            "@P1 bra.uni WAIT_DONE_%=;\n\t" \
            "bra.uni WAIT_LOOP_%=;\n\t" \
            "WAIT_DONE_%=:\n\t}" \
            :: "r"(_mbar), "r"(_parity) : "memory"); \
    } \
} while(0)

#define TCGEN05_LD_32X32B_X32(r, tmem_addr) \
    asm volatile( \
        "tcgen05.ld.sync.aligned.32x32b.x32.b32 " \
        "{%0, %1, %2, %3, %4, %5, %6, %7, " \
        " %8, %9, %10, %11, %12, %13, %14, %15, " \
        " %16, %17, %18, %19, %20, %21, %22, %23, " \
        " %24, %25, %26, %27, %28, %29, %30, %31}, [%32];" \
        : "=r"((r)[0]),  "=r"((r)[1]),  "=r"((r)[2]),  "=r"((r)[3]), \
          "=r"((r)[4]),  "=r"((r)[5]),  "=r"((r)[6]),  "=r"((r)[7]), \
          "=r"((r)[8]),  "=r"((r)[9]),  "=r"((r)[10]), "=r"((r)[11]), \
          "=r"((r)[12]), "=r"((r)[13]), "=r"((r)[14]), "=r"((r)[15]), \
          "=r"((r)[16]), "=r"((r)[17]), "=r"((r)[18]), "=r"((r)[19]), \
          "=r"((r)[20]), "=r"((r)[21]), "=r"((r)[22]), "=r"((r)[23]), \
          "=r"((r)[24]), "=r"((r)[25]), "=r"((r)[26]), "=r"((r)[27]), \
          "=r"((r)[28]), "=r"((r)[29]), "=r"((r)[30]), "=r"((r)[31]) \
        : "r"(tmem_addr))

#define TCGEN05_LD_32X32B_X16(r, tmem_addr) \
    asm volatile( \
        "tcgen05.ld.sync.aligned.32x32b.x16.b32 " \
        "{%0, %1, %2, %3, %4, %5, %6, %7, " \
        " %8, %9, %10, %11, %12, %13, %14, %15}, [%16];" \
        : "=r"((r)[0]),  "=r"((r)[1]),  "=r"((r)[2]),  "=r"((r)[3]), \
          "=r"((r)[4]),  "=r"((r)[5]),  "=r"((r)[6]),  "=r"((r)[7]), \
          "=r"((r)[8]),  "=r"((r)[9]),  "=r"((r)[10]), "=r"((r)[11]), \
          "=r"((r)[12]), "=r"((r)[13]), "=r"((r)[14]), "=r"((r)[15]) \
        : "r"(tmem_addr))

static constexpr unsigned long long SMEM_DESC_BASE_SW128 =
    (2ull << 61) | (1ull << 46) | (64ull << 32) | (1ull << 16);
#define MAKE_SMEM_DESC(a) (SMEM_DESC_BASE_SW128 | ((unsigned long long)((a) >> 4) & 0x3FFF))

__device__ __forceinline__ void mma_bf16_ss(uint32_t d, u64 ad, u64 bd,
                                            uint32_t idesc, uint32_t en) {
    asm volatile(
        "{\n\t.reg .pred p;\n\t"
        "setp.ne.u32 p, %4, 0;\n\t"
        "tcgen05.mma.cta_group::1.kind::f16 [%0], %1, %2, %3, {%5, %5, %5, %5}, p;\n\t"
        "}"
        :: "r"(d), "l"(ad), "l"(bd), "r"(idesc), "r"(en), "r"(0u)
        : "memory");
}

static constexpr uint32_t GEMM_IDESC =
    (1u << 4) | (1u << 7) | (1u << 10) | ((128u / 8) << 17) | ((128u / 16) << 24);
static constexpr uint32_t IDESC_N256 =
    (1u << 4) | (1u << 7) | (1u << 10) | ((256u / 8) << 17) | ((128u / 16) << 24);
#endif // HAS_TCGEN05

// ---------------------------------------------------------------------------
__global__ __launch_bounds__(256) void k_init(const float* __restrict__ x,
                                              const float* __restrict__ Wc,
                                              const float* __restrict__ bc) {
    int idx = blockIdx.x * 256 + threadIdx.x;
    int c  = idx & (NC - 1);
    int bt = idx >> 7;
    float v = x[bt] * Wc[c] + bc[c];
    g_h[idx]    = v;
    g_skip[idx] = 0.f;
    __nv_bfloat16 h = __float2bfloat16(v);
    g_hHi[idx] = h;
    g_hLo[idx] = __float2bfloat16(v - __bfloat162float(h));
}

// ---------------------------------------------------------------------------
__global__ __launch_bounds__(256) void k_cvtStack(
    const float* __restrict__ Wt, const float* __restrict__ Ws,
    const float* __restrict__ Wskip, const float* __restrict__ Wres)
{
    __shared__ float t[32][33];
    int id = blockIdx.x;
    int tid = threadIdx.x;
    int tx = tid & 31, ty = tid >> 5;

    const float* src;
    __nv_bfloat16 *dhi, *dlo;
    int co0, ci0, gate;
    size_t obase;
    if (id < 960) {
        int z = id / 16, rem = id % 16;
        co0 = (rem & 3) * 32; ci0 = (rem >> 2) * 32;
        int lt = z >> 1; gate = z & 1;
        src = (gate ? Ws : Wt) + (size_t)lt * 128 * 128;
        dhi = g_WgHi; dlo = g_WgLo;
        obase = (size_t)lt * 256 * 128;
    } else {
        int id2 = id - 960;
        int z = id2 / 16, rem = id2 % 16;
        co0 = (rem & 3) * 32; ci0 = (rem >> 2) * 32;
        int l = z >> 1; gate = z & 1;
        src = (gate ? Wres : Wskip) + (size_t)l * 128 * 128;
        dhi = g_WpHi; dlo = g_WpLo;
        obase = (size_t)l * 256 * 128;
    }
    #pragma unroll
    for (int r = 0; r < 4; r++)
        t[ty + r*8][tx] = src[(ci0 + ty + r*8) * 128 + co0 + tx];
    __syncthreads();
    #pragma unroll
    for (int r = 0; r < 4; r++) {
        float v = t[tx][ty + r*8];
        int n = gate * 128 + co0 + ty + r*8;
        size_t o = obase + (size_t)n * 128 + ci0 + tx;
        __nv_bfloat16 h = __float2bfloat16(v);
        dhi[o] = h;
        dlo[o] = __float2bfloat16(v - __bfloat162float(h));
    }
}

__global__ void k_cvtWhead(const float* __restrict__ W1, const float* __restrict__ W2,
                           __nv_bfloat16* __restrict__ w1h, __nv_bfloat16* __restrict__ w1l,
                           __nv_bfloat16* __restrict__ w2h, __nv_bfloat16* __restrict__ w2l) {
    __shared__ float t[32][33];
    int id = blockIdx.x;
    const float* src; __nv_bfloat16 *dhi, *dlo;
    int K, N, n0, k0, tap;
    if (id < 768) {
        tap = id / 256; int rem = id % 256;
        n0 = (rem & 63) * 32; k0 = (rem >> 6) * 32;
        src = W1; dhi = w1h; dlo = w1l; K = 128; N = 2048;
    } else {
        id -= 768;
        tap = id / 512; int rem = id % 512;
        n0 = (rem & 7) * 32; k0 = (rem >> 3) * 32;
        src = W2; dhi = w2h; dlo = w2l; K = 2048; N = 256;
    }
    int tx = threadIdx.x, ty = threadIdx.y;
    #pragma unroll
    for (int r = 0; r < 4; r++)
        t[ty + r*8][tx] = src[((size_t)tap*K + k0 + ty + r*8) * N + n0 + tx];
    __syncthreads();
    #pragma unroll
    for (int r = 0; r < 4; r++) {
        float v = t[tx][ty + r*8];
        __nv_bfloat16 h = __float2bfloat16(v);
        __nv_bfloat16 l = __float2bfloat16(v - __bfloat162float(h));
        size_t o = ((size_t)tap*N + n0 + ty + r*8) * K + k0 + tx;
        dhi[o] = h; dlo[o] = l;
    }
}

// ---------------------------------------------------------------------------
__global__ __launch_bounds__(256) void k_condpre(
    const float* __restrict__ cond,
    const float* __restrict__ Dt, const float* __restrict__ Ds,
    const float* __restrict__ Bt, const float* __restrict__ Bs,
    const float* __restrict__ bt, const float* __restrict__ bs, int l)
{
    const int tid = threadIdx.x;
    const int co = (tid & 31) << 2;
    const int gate = (tid >> 5) & 1;
    const int tq = tid >> 6;
    const int t0 = blockIdx.x * 8 + tq;

    __shared__ float sc[NB][NCOND];
    if (tid < NB * NCOND) sc[tid >> 4][tid & 15] = cond[tid];
    __syncthreads();

    const float* D  = gate ? Ds : Dt;
    const float* Bm = gate ? Bs : Bt;
    float4 bias = *(const float4*)((gate ? bs : bt) + l * 128 + co);

    float4 acc[2][NB];
    #pragma unroll
    for (int tt = 0; tt < 2; tt++)
        #pragma unroll
        for (int b = 0; b < NB; b++) acc[tt][b] = make_float4(0.f, 0.f, 0.f, 0.f);

    #pragma unroll 4
    for (int c = 0; c < NCOND; c++) {
        size_t base = (((size_t)l * NCOND + c) * TT + t0) * 128 + co;
        float4 d0 = *(const float4*)(D + base);
        float4 d1 = *(const float4*)(D + base + 4 * 128);
        #pragma unroll
        for (int b = 0; b < NB; b++) {
            float s = sc[b][c];
            acc[0][b].x = fmaf(s, d0.x, acc[0][b].x);
            acc[0][b].y = fmaf(s, d0.y, acc[0][b].y);
            acc[0][b].z = fmaf(s, d0.z, acc[0][b].z);
            acc[0][b].w = fmaf(s, d0.w, acc[0][b].w);
            acc[1][b].x = fmaf(s, d1.x, acc[1][b].x);
            acc[1][b].y = fmaf(s, d1.y, acc[1][b].y);
            acc[1][b].z = fmaf(s, d1.z, acc[1][b].z);
            acc[1][b].w = fmaf(s, d1.w, acc[1][b].w);
        }
    }
    #pragma unroll
    for (int tt = 0; tt < 2; tt++) {
        int t = t0 + tt * 4;
        float4 bm = *(const float4*)(Bm + ((size_t)l * TT + t) * 128 + co);
        bm.x += bias.x; bm.y += bias.y; bm.z += bias.z; bm.w += bias.w;
        #pragma unroll
        for (int b = 0; b < NB; b++) {
            float4 v = acc[tt][b];
            v.x += bm.x; v.y += bm.y; v.z += bm.z; v.w += bm.w;
            *(float4*)(g_tcond + (((size_t)l * NB + b) * TT + t) * 256
                       + gate * 128 + co) = v;
        }
    }
}

// ---------------------------------------------------------------------------
// Fused residual layer: 1024 threads (round-16 validated, unchanged).
// ---------------------------------------------------------------------------
#define LAYER_SMEM 200704

__global__ __launch_bounds__(1024, 1) void k_layer(
    int l, int d, const float* __restrict__ bskip, const float* __restrict__ bres)
{
#if HAS_TCGEN05
    extern __shared__ char dsm[];
    const int tid = threadIdx.x;
    const int wid = tid >> 5;
    const int lane = tid & 31;

    uint32_t raw = smem_to_u32(dsm);
    uint32_t abase = (raw + 1023) & ~1023u;
    char* hdr = dsm + (abase - raw);
    char* G   = hdr + 2048;
    const uint32_t hdr_a = abase;
    const uint32_t G_a   = abase + 2048;

    const int b  = blockIdx.x >> 4;
    const int t0 = (blockIdx.x & 15) << 7;

    if (tid == 0) {
        MBARRIER_INIT(hdr_a + 8, 1);
        MBARRIER_INIT(hdr_a + 16, 1);
    }
    if (wid == 0) TCGEN05_ALLOC(hdr_a, 512);
    __syncthreads();

    uint32_t tmem;
    asm volatile("ld.shared.b32 %0, [%1];" : "=r"(tmem) : "r"(hdr_a));

    int phase[2] = {0, 0};

    for (int ch = 0; ch < 6; ch++) {
        const int buf = ch & 1;
        char* Gb = G + buf * 98304;
        const uint32_t Gb_a = G_a + buf * 98304;
        const int tap = ch >> 1;
        const int ci0 = (ch & 1) << 6;

        uint4 va[2];
        const int r8 = tid >> 3, oc = tid & 7;
        {
            int trow = t0 + r8 + (tap - 1) * d;
            bool ok = (unsigned)trow < (unsigned)TT;
            size_t goff = ((size_t)(b * TT + (ok ? trow : 0))) * NC + ci0 + oc * 8;
            if (ok) {
                va[0] = *(const uint4*)(g_hHi + goff);
                va[1] = *(const uint4*)(g_hLo + goff);
            } else {
                va[0] = make_uint4(0,0,0,0);
                va[1] = make_uint4(0,0,0,0);
            }
        }
        uint4 wb[4];
        const int rb = tid >> 2, cb = tid & 3;
        {
            size_t woff = (((size_t)(l * 3 + tap)) * 256 + rb) * 128 + ci0 + cb * 16;
            wb[0] = *(const uint4*)(g_WgHi + woff);
            wb[1] = *(const uint4*)(g_WgHi + woff + 8);
            wb[2] = *(const uint4*)(g_WgLo + woff);
            wb[3] = *(const uint4*)(g_WgLo + woff + 8);
        }

        if (ch >= 2) {
            MBARRIER_WAIT_PARITY(hdr_a + 8 + 8 * buf, phase[buf]);
            phase[buf] ^= 1;
        }

        {
            uint32_t so = r8 * 128 + (((uint32_t)(oc ^ (r8 & 7))) << 4);
            *(uint4*)(Gb + so)         = va[0];
            *(uint4*)(Gb + 16384 + so) = va[1];
        }
        #pragma unroll
        for (int q = 0; q < 2; q++) {
            int c = cb * 2 + q;
            uint32_t so = rb * 128 + (((uint32_t)(c ^ (rb & 7))) << 4);
            *(uint4*)(Gb + 32768 + so) = wb[q];
            *(uint4*)(Gb + 65536 + so) = wb[2 + q];
        }
        FENCE_PROXY_ASYNC_SHARED_CTA();
        __syncthreads();

        if (wid == 0 && elect_one_pred()) {
            u64 dAh = MAKE_SMEM_DESC(Gb_a);
            u64 dAl = MAKE_SMEM_DESC(Gb_a + 16384);
            u64 dBh = MAKE_SMEM_DESC(Gb_a + 32768);
            u64 dBl = MAKE_SMEM_DESC(Gb_a + 65536);
            uint32_t en = (ch != 0);
            #pragma unroll
            for (int ks = 0; ks < 4; ks++) {
                mma_bf16_ss(tmem, dAh + 2*ks, dBh + 2*ks, IDESC_N256, en); en = 1;
                mma_bf16_ss(tmem, dAh + 2*ks, dBl + 2*ks, IDESC_N256, 1);
                mma_bf16_ss(tmem, dAl + 2*ks, dBh + 2*ks, IDESC_N256, 1);
            }
            TCGEN05_COMMIT(hdr_a + 8 + 8 * buf);
        }
    }

    MBARRIER_WAIT_PARITY(hdr_a + 8,  phase[0]);
    MBARRIER_WAIT_PARITY(hdr_a + 16, phase[1]);
    const int postPh = phase[0] ^ 1;
    TCGEN05_FENCE_AFTER();
    __syncthreads();

    float* tcS = (float*)(G + 65536);
    {
        const float* tcg = g_tcond + (((size_t)l * NB + b) * TT + t0) * 256;
        #pragma unroll
        for (int k = 0; k < 8; k++) {
            int i4 = tid + k * 1024;
            int row = i4 >> 6, c4 = (i4 & 63) << 2;
            float4 v = *(const float4*)(tcg + (size_t)row * 256 + c4);
            *(float4*)(tcS + row * 260 + c4) = v;
        }
    }
    __syncthreads();

    {
        const int row = (wid & 3) * 32 + lane;
        const int c0 = (wid >> 2) * 16;
        const float* trow_ = tcS + row * 260;
        uint32_t rt[16], rs[16];
        TCGEN05_LD_32X32B_X16(rt, tmem + c0);
        TCGEN05_LD_32X32B_X16(rs, tmem + 128 + c0);
        TCGEN05_WAIT_LD();
        #pragma unroll
        for (int j = 0; j < 16; j += 4) {
            int c = c0 + j;
            float4 ta = *(const float4*)(trow_ + c);
            float4 tx = *(const float4*)(trow_ + 128 + c);
            float av[4] = {__uint_as_float(rt[j])   + ta.x,
                           __uint_as_float(rt[j+1]) + ta.y,
                           __uint_as_float(rt[j+2]) + ta.z,
                           __uint_as_float(rt[j+3]) + ta.w};
            float xv[4] = {__uint_as_float(rs[j])   + tx.x,
                           __uint_as_float(rs[j+1]) + tx.y,
                           __uint_as_float(rs[j+2]) + tx.z,
                           __uint_as_float(rs[j+3]) + tx.w};
            __nv_bfloat16 hv[4], lv[4];
            #pragma unroll
            for (int q = 0; q < 4; q++) {
                float gv = gate_act(av[q], xv[q]);
                hv[q] = __float2bfloat16(gv);
                lv[q] = __float2bfloat16(gv - __bfloat162float(hv[q]));
            }
            uint32_t off = row * 128 + (c & 63) * 2;
            off ^= (off >> 3) & 0x70;
            char* atp = G + ((c >> 6) * 32768);
            *(uint2*)(atp + off)         = *(const uint2*)hv;
            *(uint2*)(atp + 16384 + off) = *(const uint2*)lv;
        }
    }
    __syncthreads();

    {
        const int r = tid >> 2, cb2 = tid & 3;
        size_t woff = ((size_t)l * 256 + r) * 128;
        #pragma unroll
        for (int cc = 0; cc < 2; cc++) {
            char* dst = G + 65536 + cc * 65536;
            #pragma unroll
            for (int q = 0; q < 2; q++) {
                int c = cb2 * 2 + q;
                uint32_t so = r * 128 + (((uint32_t)(c ^ (r & 7))) << 4);
                *(uint4*)(dst + so)         = *(const uint4*)(g_WpHi + woff + cc*64 + c*8);
                *(uint4*)(dst + 32768 + so) = *(const uint4*)(g_WpLo + woff + cc*64 + c*8);
            }
        }
    }
    FENCE_PROXY_ASYNC_SHARED_CTA();
    __syncthreads();

    if (wid == 0 && elect_one_pred()) {
        uint32_t en = 0;
        #pragma unroll
        for (int cc = 0; cc < 2; cc++) {
            u64 dAh = MAKE_SMEM_DESC(G_a + cc * 32768);
            u64 dAl = MAKE_SMEM_DESC(G_a + cc * 32768 + 16384);
            u64 dBh = MAKE_SMEM_DESC(G_a + 65536 + cc * 65536);
            u64 dBl = MAKE_SMEM_DESC(G_a + 65536 + cc * 65536 + 32768);
            #pragma unroll
            for (int ks = 0; ks < 4; ks++) {
                mma_bf16_ss(tmem + 256, dAh + 2*ks, dBh + 2*ks, IDESC_N256, en); en = 1;
                mma_bf16_ss(tmem + 256, dAh + 2*ks, dBl + 2*ks, IDESC_N256, 1);
                mma_bf16_ss(tmem + 256, dAl + 2*ks, dBh + 2*ks, IDESC_N256, 1);
            }
        }
        TCGEN05_COMMIT(hdr_a + 8);
    }
    MBARRIER_WAIT_PARITY(hdr_a + 8, postPh);
    TCGEN05_FENCE_AFTER();
    __syncthreads();

    float* st = (float*)G;
    {
        const int row = (wid & 3) * 32 + lane;
        const int c0 = (wid >> 2) * 32;
        uint32_t ra[32];
        TCGEN05_LD_32X32B_X32(ra, tmem + 256 + c0);
        TCGEN05_WAIT_LD();
        #pragma unroll
        for (int j = 0; j < 32; j += 4) {
            float4 v1 = make_float4(__uint_as_float(ra[j]),   __uint_as_float(ra[j+1]),
                                    __uint_as_float(ra[j+2]), __uint_as_float(ra[j+3]));
            *(float4*)(st + row * 260 + c0 + j) = v1;
        }
    }
    __syncthreads();

    {
        const size_t gbase = ((size_t)(b * TT + t0)) * NC;
        const bool lastL = (l == NL - 1);
        #pragma unroll
        for (int k = 0; k < 4; k++) {
            int e = tid + k * 1024;
            int row = e >> 5, c4 = (e & 31) << 2;
            float4 dsk = *(const float4*)(st + row * 260 + c4);
            float4 bk4 = *(const float4*)(bskip + l * 128 + c4);
            size_t go = gbase + (size_t)row * NC + c4;
            float4 sk = *(const float4*)(g_skip + go);
            sk.x += dsk.x + bk4.x; sk.y += dsk.y + bk4.y;
            sk.z += dsk.z + bk4.z; sk.w += dsk.w + bk4.w;
            if (!lastL) {
                float4 dre = *(const float4*)(st + row * 260 + 128 + c4);
                float4 br4 = *(const float4*)(bres  + l * 128 + c4);
                float4 hh = *(const float4*)(g_h + go);
                hh.x += dre.x + br4.x; hh.y += dre.y + br4.y;
                hh.z += dre.z + br4.z; hh.w += dre.w + br4.w;
                *(float4*)(g_skip + go) = sk;
                *(float4*)(g_h + go) = hh;
                float hq[4] = {hh.x, hh.y, hh.z, hh.w};
                __nv_bfloat16 hv[4], lv[4];
                #pragma unroll
                for (int q = 0; q < 4; q++) {
                    hv[q] = __float2bfloat16(hq[q]);
                    lv[q] = __float2bfloat16(hq[q] - __bfloat162float(hv[q]));
                }
                *(uint2*)(g_hHi + go) = *(const uint2*)hv;
                *(uint2*)(g_hLo + go) = *(const uint2*)lv;
            } else {
                float sq[4] = {sk.x, sk.y, sk.z, sk.w};
                __nv_bfloat16 hv[4], lv[4];
                #pragma unroll
                for (int q = 0; q < 4; q++) {
                    hv[q] = __float2bfloat16(sq[q]);
                    lv[q] = __float2bfloat16(sq[q] - __bfloat162float(hv[q]));
                }
                *(uint2*)(g_skipHi + go) = *(const uint2*)hv;
                *(uint2*)(g_skipLo + go) = *(const uint2*)lv;
            }
        }
    }
    __syncthreads();
    if (wid == 0) {
        TCGEN05_RELINQUISH_ALLOC_PERMIT();
        TCGEN05_DEALLOC(tmem, 512);
    }
#endif // HAS_TCGEN05
}

// ---------------------------------------------------------------------------
// Head GEMM-conv3, TWO N-tiles per CTA, now 512 threads (16 warps).
// ---------------------------------------------------------------------------
#define GEMM_SMEM 200704

template<bool WB16>
__global__ __launch_bounds__(512, 1) void k_gemm(
    const __nv_bfloat16* __restrict__ aHi, const __nv_bfloat16* __restrict__ aLo,
    const __nv_bfloat16* __restrict__ wHi, const __nv_bfloat16* __restrict__ wLo,
    const float* __restrict__ bias,
    __nv_bfloat16* __restrict__ oHi, __nv_bfloat16* __restrict__ oLo,
    float* __restrict__ oF, int Cin, int CO)
{
#if HAS_TCGEN05
    extern __shared__ char dsm[];
    const int tid = threadIdx.x;
    const int wid = tid >> 5;
    const int lane = tid & 31;

    uint32_t raw = smem_to_u32(dsm);
    uint32_t abase = (raw + 1023) & ~1023u;
    char* hdr   = dsm + (abase - raw);
    char* G     = hdr + 2048;
    const uint32_t hdr_a = abase;
    const uint32_t G_a   = abase + 2048;
    float* sbias = (float*)(hdr + 1024);

    const int b  = blockIdx.x >> 4;
    const int t0 = (blockIdx.x & 15) * 128;
    const int n0 = blockIdx.y * 256;

    if (tid == 0) {
        MBARRIER_INIT(hdr_a + 8, 1);
        MBARRIER_INIT(hdr_a + 16, 1);
    }
    if (wid == 0) TCGEN05_ALLOC(hdr_a, 256);
    if (tid < 256) sbias[tid] = bias[n0 + tid];
    __syncthreads();

    uint32_t tmem;
    asm volatile("ld.shared.b32 %0, [%1];" : "=r"(tmem) : "r"(hdr_a));

    const int nci = Cin >> 6;
    const int nchunks = 3 * nci;
    const size_t aBatch = (size_t)b * TT * Cin;

    int phase[2] = {0, 0};

    for (int ch = 0; ch < nchunks; ch++) {
        const int buf = ch & 1;
        char* tb = G + buf * 98304;
        const uint32_t tb_a = G_a + buf * 98304;

        const int tap = ch / nci;
        const int ci0 = (ch - tap * nci) << 6;
        const size_t bBase0 = ((size_t)tap * CO + n0) * Cin + ci0;
        const int c = tid & 7;
        const int rbase = tid >> 3;          // 0..63

        // prefetch A + B(tile0): 2 rows per thread
        uint4 va[4], vb0[4];
        #pragma unroll
        for (int p = 0; p < 2; p++) {
            int r = p * 64 + rbase;
            int trow = t0 + r + tap - 1;
            if ((unsigned)trow < (unsigned)TT) {
                size_t off = aBatch + (size_t)trow * Cin + ci0 + c * 8;
                va[p]     = *(const uint4*)(aHi + off);
                va[2 + p] = *(const uint4*)(aLo + off);
            } else {
                va[p] = make_uint4(0,0,0,0);
                va[2 + p] = make_uint4(0,0,0,0);
            }
            size_t bo = bBase0 + (size_t)r * Cin + c * 8;
            vb0[p]     = *(const uint4*)(wHi + bo);
            vb0[2 + p] = *(const uint4*)(wLo + bo);
        }

        if (ch >= 2) {
            MBARRIER_WAIT_PARITY(hdr_a + 8 + 8 * buf, phase[buf]);
            phase[buf] ^= 1;
        }

        #pragma unroll
        for (int p = 0; p < 2; p++) {
            int r = p * 64 + rbase;
            uint32_t so = r * 128 + (((uint32_t)(c ^ (r & 7))) << 4);
            *(uint4*)(tb + so)         = va[p];
            *(uint4*)(tb + 16384 + so) = va[2 + p];
            *(uint4*)(tb + 32768 + so) = vb0[p];
            *(uint4*)(tb + 49152 + so) = vb0[2 + p];
        }
        {
            const size_t bBase1 = bBase0 + (size_t)128 * Cin;
            #pragma unroll
            for (int p = 0; p < 2; p++) {
                int r = p * 64 + rbase;
                size_t bo = bBase1 + (size_t)r * Cin + c * 8;
                uint4 h4 = *(const uint4*)(wHi + bo);
                uint4 l4 = *(const uint4*)(wLo + bo);
                uint32_t so = r * 128 + (((uint32_t)(c ^ (r & 7))) << 4);
                *(uint4*)(tb + 65536 + so) = h4;
                *(uint4*)(tb + 81920 + so) = l4;
            }
        }
        FENCE_PROXY_ASYNC_SHARED_CTA();
        __syncthreads();

        if (wid == 0 && elect_one_pred()) {
            u64 dAh  = MAKE_SMEM_DESC(tb_a);
            u64 dAl  = MAKE_SMEM_DESC(tb_a + 16384);
            u64 dB0h = MAKE_SMEM_DESC(tb_a + 32768);
            u64 dB0l = MAKE_SMEM_DESC(tb_a + 49152);
            u64 dB1h = MAKE_SMEM_DESC(tb_a + 65536);
            u64 dB1l = MAKE_SMEM_DESC(tb_a + 81920);
            uint32_t en = (ch != 0);
            #pragma unroll
            for (int ks = 0; ks < 4; ks++) {
                mma_bf16_ss(tmem,       dAh + 2*ks, dB0h + 2*ks, GEMM_IDESC, en);
                mma_bf16_ss(tmem + 128, dAh + 2*ks, dB1h + 2*ks, GEMM_IDESC, en);
                en = 1;
                mma_bf16_ss(tmem,       dAh + 2*ks, dB0l + 2*ks, GEMM_IDESC, 1);
                mma_bf16_ss(tmem,       dAl + 2*ks, dB0h + 2*ks, GEMM_IDESC, 1);
                mma_bf16_ss(tmem + 128, dAh + 2*ks, dB1l + 2*ks, GEMM_IDESC, 1);
                mma_bf16_ss(tmem + 128, dAl + 2*ks, dB1h + 2*ks, GEMM_IDESC, 1);
            }
            TCGEN05_COMMIT(hdr_a + 8 + 8 * buf);
        }
    }

    MBARRIER_WAIT_PARITY(hdr_a + 8,  phase[0]);
    MBARRIER_WAIT_PARITY(hdr_a + 16, phase[1]);
    TCGEN05_FENCE_AFTER();
    __syncthreads();

    // staged epilogue per n-tile, 16 warps: rows (wid&3)*32, cols (wid>>2)*32
    #pragma unroll 1
    for (int nt = 0; nt < 2; nt++) {
        const uint32_t dbase = tmem + nt * 128;
        const int nb = n0 + nt * 128;
        if (WB16) {
            char* hiS = G;
            char* loS = G + 34816;
            {
                const int m = (wid & 3) * 32 + lane;
                const int c0 = (wid >> 2) * 32;
                uint32_t r32[32];
                TCGEN05_LD_32X32B_X32(r32, dbase + c0);
                TCGEN05_WAIT_LD();
                #pragma unroll
                for (int j = 0; j < 32; j += 2) {
                    __nv_bfloat16 hv[2], lv[2];
                    #pragma unroll
                    for (int q = 0; q < 2; q++) {
                        float v = __uint_as_float(r32[j+q]) + sbias[nt*128 + c0 + j + q];
                        v = fmaxf(v, 0.f);
                        hv[q] = __float2bfloat16(v);
                        lv[q] = __float2bfloat16(v - __bfloat162float(hv[q]));
                    }
                    uint32_t so = m * 272 + (c0 + j) * 2;
                    *(uint32_t*)(hiS + so) = *(const uint32_t*)hv;
                    *(uint32_t*)(loS + so) = *(const uint32_t*)lv;
                }
            }
            __syncthreads();
            #pragma unroll
            for (int k = 0; k < 4; k++) {
                int e = tid + k * 512;
                int row = e >> 4, cu = e & 15;
                uint4 h4 = *(const uint4*)(hiS + row * 272 + cu * 16);
                uint4 l4 = *(const uint4*)(loS + row * 272 + cu * 16);
                size_t o = (size_t)(b * TT + t0 + row) * CO + nb + cu * 8;
                *(uint4*)(oHi + o) = h4;
                *(uint4*)(oLo + o) = l4;
            }
            __syncthreads();
        } else {
            float* fS = (float*)G;
            {
                const int m = (wid & 3) * 32 + lane;
                const int c0 = (wid >> 2) * 32;
                uint32_t r32[32];
                TCGEN05_LD_32X32B_X32(r32, dbase + c0);
                TCGEN05_WAIT_LD();
                #pragma unroll
                for (int j = 0; j < 32; j += 4) {
                    float4 v;
                    v.x = fmaxf(__uint_as_float(r32[j])   + sbias[nt*128 + c0+j],   0.f);
                    v.y = fmaxf(__uint_as_float(r32[j+1]) + sbias[nt*128 + c0+j+1], 0.f);
                    v.z = fmaxf(__uint_as_float(r32[j+2]) + sbias[nt*128 + c0+j+2], 0.f);
                    v.w = fmaxf(__uint_as_float(r32[j+3]) + sbias[nt*128 + c0+j+3], 0.f);
                    *(float4*)(fS + m * 132 + c0 + j) = v;
                }
            }
            __syncthreads();
            #pragma unroll
            for (int k = 0; k < 8; k++) {
                int e = tid + k * 512;
                int row = e >> 5, c4 = (e & 31) << 2;
                float4 v = *(const float4*)(fS + row * 132 + c4);
                *(float4*)(oF + (size_t)(b * TT + t0 + row) * CO + nb + c4) = v;
            }
            __syncthreads();
        }
    }

    if (wid == 0) {
        TCGEN05_RELINQUISH_ALLOC_PERMIT();
        TCGEN05_DEALLOC(tmem, 256);
    }
#endif // HAS_TCGEN05
}

// ---------------------------------------------------------------------------
__global__ __launch_bounds__(128) void k_head3(const float* __restrict__ W3,
                                               const float* __restrict__ b3,
                                               float* __restrict__ out)
{
    int row  = blockIdx.x * 4 + (threadIdx.x >> 5);
    int lane = threadIdx.x & 31;
    const float* p = g_out2 + (size_t)row * 256;
    float s = 0.f;
    #pragma unroll
    for (int i = 0; i < 8; i++) s = fmaf(p[lane + 32 * i], W3[lane + 32 * i], s);
    #pragma unroll
    for (int o = 16; o; o >>= 1) s += __shfl_xor_sync(0xffffffffu, s, o);
    if (lane == 0) out[row] = tanhf(s + b3[0]);
}

// ---------------------------------------------------------------------------
static cudaStream_t s_side = nullptr;
static cudaEvent_t  s_evFork = nullptr;
static cudaEvent_t  s_evW = nullptr;
static cudaEvent_t  s_evL[NL];

extern "C" void kernel_launch(void* const* d_in, const int* in_sizes, int n_in,
                              void* d_out, int out_size) {
    const float* x     = (const float*)d_in[0];
    const float* cond  = (const float*)d_in[1];
    const float* Wc    = (const float*)d_in[2];
    const float* bc    = (const float*)d_in[3];
    const float* Wt    = (const float*)d_in[4];
    const float* bt    = (const float*)d_in[5];
    const float* Ws    = (const float*)d_in[6];
    const float* bs    = (const float*)d_in[7];
    const float* Dt    = (const float*)d_in[8];
    const float* Bt    = (const float*)d_in[9];
    const float* Ds    = (const float*)d_in[10];
    const float* Bs    = (const float*)d_in[11];
    const float* Wskip = (const float*)d_in[12];
    const float* bskip = (const float*)d_in[13];
    const float* Wres  = (const float*)d_in[14];
    const float* bres  = (const float*)d_in[15];
    const float* W1    = (const float*)d_in[16];
    const float* b1    = (const float*)d_in[17];
    const float* W2    = (const float*)d_in[18];
    const float* b2    = (const float*)d_in[19];
    const float* W3    = (const float*)d_in[20];
    const float* b3    = (const float*)d_in[21];
    float* out = (float*)d_out;

    if (!s_side) {
        cudaStreamCreateWithFlags(&s_side, cudaStreamNonBlocking);
        cudaEventCreateWithFlags(&s_evFork, cudaEventDisableTiming);
        cudaEventCreateWithFlags(&s_evW, cudaEventDisableTiming);
        for (int l = 0; l < NL; l++)
            cudaEventCreateWithFlags(&s_evL[l], cudaEventDisableTiming);
    }

    cudaFuncSetAttribute(k_layer, cudaFuncAttributeMaxDynamicSharedMemorySize, LAYER_SMEM);
    cudaFuncSetAttribute(k_gemm<true>,  cudaFuncAttributeMaxDynamicSharedMemorySize, GEMM_SMEM);
    cudaFuncSetAttribute(k_gemm<false>, cudaFuncAttributeMaxDynamicSharedMemorySize, GEMM_SMEM);

    __nv_bfloat16 *skipHi, *skipLo, *w1h, *w1l, *w2h, *w2l, *o1h, *o1l;
    float* out2p;
    cudaGetSymbolAddress((void**)&skipHi, g_skipHi);
    cudaGetSymbolAddress((void**)&skipLo, g_skipLo);
    cudaGetSymbolAddress((void**)&w1h, g_W1tHi);
    cudaGetSymbolAddress((void**)&w1l, g_W1tLo);
    cudaGetSymbolAddress((void**)&w2h, g_W2tHi);
    cudaGetSymbolAddress((void**)&w2l, g_W2tLo);
    cudaGetSymbolAddress((void**)&o1h, g_out1Hi);
    cudaGetSymbolAddress((void**)&o1l, g_out1Lo);
    cudaGetSymbolAddress((void**)&out2p, g_out2);

    const int dil[NL] = {1, 2, 4, 8, 16, 32, 64, 128, 256, 512};

    // main stream; k_layer(0) is the 4th launch (ncu profiles the 4th)
    k_condpre<<<TT/8, 256>>>(cond, Dt, Ds, Bt, Bs, bt, bs, 0);     // 1
    k_cvtStack<<<1280, 256>>>(Wt, Ws, Wskip, Wres);                // 2
    k_init<<<NB * TT * NC / 256, 256>>>(x, Wc, bc);                // 3
    k_layer<<<NB * (TT/128), 1024, LAYER_SMEM>>>(0, dil[0], bskip, bres); // 4

    // side stream: head-weight conversion + remaining condpre slices
    cudaEventRecord(s_evFork, 0);
    cudaStreamWaitEvent(s_side, s_evFork, 0);
    k_cvtWhead<<<2304, dim3(32, 8), 0, s_side>>>(W1, W2, w1h, w1l, w2h, w2l);
    cudaEventRecord(s_evW, s_side);
    for (int l = 1; l < NL; l++) {
        k_condpre<<<TT/8, 256, 0, s_side>>>(cond, Dt, Ds, Bt, Bs, bt, bs, l);
        cudaEventRecord(s_evL[l], s_side);
    }
    for (int l = 1; l < NL; l++) {
        cudaStreamWaitEvent(0, s_evL[l], 0);
        k_layer<<<NB * (TT/128), 1024, LAYER_SMEM>>>(l, dil[l], bskip, bres);
    }

    // heads (gated on head-weight conversion)
    cudaStreamWaitEvent(0, s_evW, 0);
    k_gemm<true><<<dim3(128, 8), 512, GEMM_SMEM>>>(
        skipHi, skipLo, w1h, w1l, b1, o1h, o1l, nullptr, 128, 2048);
    k_gemm<false><<<dim3(128, 1), 512, GEMM_SMEM>>>(
        o1h, o1l, w2h, w2l, b2, nullptr, nullptr, out2p, 2048, 256);

    k_head3<<<NB * TT / 4, 128>>>(W3, b3, out);
}